// round 5
// baseline (speedup 1.0000x reference)
#include <cuda_runtime.h>
#include <cstdint>
#include <cstddef>

#define BSZ 4
#define SEQ 4096
#define DM  2048
#define NH  16
#define DH  128
#define MROWS (BSZ*SEQ)               // 16384
#define OUT_ELEMS ((size_t)MROWS*DM)  // 33554432
#define STATE_ELEMS ((size_t)BSZ*NH*DH*DH)
#define QSCALE 0.08838834764831845f   // 1/sqrt(128)

// ---------------- scratch (device globals: allocation-free rule) ------------
__device__ float  g_q [(size_t)MROWS*DM];
__device__ int8_t g_k [(size_t)MROWS*DM];
__device__ int8_t g_v [(size_t)MROWS*DM];
__device__ float  g_ao[(size_t)MROWS*DM];

// ---------------------------------------------------------------------------
// GEMM (NT): C[m,n] = sum_k A[m,k]*B[n,k].  A:[16384,2048]  B:[2048,2048]
// 128x128 block tile, BK=16, 256 threads, 8x8 per thread, double buffered.
// MODE 0: plain fp32 out.  MODE 1: fp32 out * QSCALE.
// MODE 2: sign epilogue -> int8, two-level fp32 accumulation (flush the
//         64-term partial every 4 k-tiles) -> pre-sign rms error ~2.4e-7.
// ---------------------------------------------------------------------------
template<int MODE>
__global__ void __launch_bounds__(256)
gemm_nt(const float* __restrict__ A, const float* __restrict__ B,
        void* __restrict__ Cout)
{
    constexpr int K = DM, N = DM, BK = 16, NT = K / BK;
    __shared__ float As[2][BK][132];
    __shared__ float Bs[2][BK][132];

    const int tid = threadIdx.x;
    const int m0 = blockIdx.y * 128, n0 = blockIdx.x * 128;
    const int lr = tid >> 2;            // 0..63
    const int lk = (tid & 3) << 2;      // 0,4,8,12

    const float* Ag  = A + (size_t)(m0 + lr) * K + lk;
    const float* Ag2 = Ag + (size_t)64 * K;
    const float* Bg  = B + (size_t)(n0 + lr) * K + lk;
    const float* Bg2 = Bg + (size_t)64 * K;

    // prologue: tile 0
    {
        float4 a0 = *(const float4*)(Ag);
        float4 a1 = *(const float4*)(Ag2);
        float4 b0 = *(const float4*)(Bg);
        float4 b1 = *(const float4*)(Bg2);
        As[0][lk+0][lr]    = a0.x; As[0][lk+1][lr]    = a0.y;
        As[0][lk+2][lr]    = a0.z; As[0][lk+3][lr]    = a0.w;
        As[0][lk+0][lr+64] = a1.x; As[0][lk+1][lr+64] = a1.y;
        As[0][lk+2][lr+64] = a1.z; As[0][lk+3][lr+64] = a1.w;
        Bs[0][lk+0][lr]    = b0.x; Bs[0][lk+1][lr]    = b0.y;
        Bs[0][lk+2][lr]    = b0.z; Bs[0][lk+3][lr]    = b0.w;
        Bs[0][lk+0][lr+64] = b1.x; Bs[0][lk+1][lr+64] = b1.y;
        Bs[0][lk+2][lr+64] = b1.z; Bs[0][lk+3][lr+64] = b1.w;
    }
    __syncthreads();

    const int ty = tid >> 4, tx = tid & 15;
    const int r0 = ty * 8, c0 = tx * 8;

    float tmp[8][8];   // segment partial (MODE 2) or full accumulator (0/1)
    float acc[8][8];   // long accumulator (MODE 2 only)
#pragma unroll
    for (int i = 0; i < 8; i++)
#pragma unroll
        for (int j = 0; j < 8; j++) {
            tmp[i][j] = 0.f;
            if (MODE == 2) acc[i][j] = 0.f;
        }

    for (int t = 0; t < NT; t++) {
        const int cur = t & 1;
        float4 na0, na1, nb0, nb1;
        const bool more = (t + 1 < NT);
        if (more) {
            const int off = (t + 1) * BK;
            na0 = *(const float4*)(Ag  + off);
            na1 = *(const float4*)(Ag2 + off);
            nb0 = *(const float4*)(Bg  + off);
            nb1 = *(const float4*)(Bg2 + off);
        }
#pragma unroll
        for (int kk = 0; kk < BK; kk++) {
            float4 x0 = *(const float4*)&As[cur][kk][r0];
            float4 x1 = *(const float4*)&As[cur][kk][r0 + 4];
            float4 y0 = *(const float4*)&Bs[cur][kk][c0];
            float4 y1 = *(const float4*)&Bs[cur][kk][c0 + 4];
            float ra[8] = {x0.x, x0.y, x0.z, x0.w, x1.x, x1.y, x1.z, x1.w};
            float rb[8] = {y0.x, y0.y, y0.z, y0.w, y1.x, y1.y, y1.z, y1.w};
#pragma unroll
            for (int i = 0; i < 8; i++)
#pragma unroll
                for (int j = 0; j < 8; j++)
                    tmp[i][j] = fmaf(ra[i], rb[j], tmp[i][j]);
        }
        if (MODE == 2) {
            if ((t & 3) == 3) {   // flush every 64 k-terms (includes t=127)
#pragma unroll
                for (int i = 0; i < 8; i++)
#pragma unroll
                    for (int j = 0; j < 8; j++) {
                        acc[i][j] += tmp[i][j];
                        tmp[i][j] = 0.f;
                    }
            }
        }
        if (more) {
            const int nb = cur ^ 1;
            As[nb][lk+0][lr]    = na0.x; As[nb][lk+1][lr]    = na0.y;
            As[nb][lk+2][lr]    = na0.z; As[nb][lk+3][lr]    = na0.w;
            As[nb][lk+0][lr+64] = na1.x; As[nb][lk+1][lr+64] = na1.y;
            As[nb][lk+2][lr+64] = na1.z; As[nb][lk+3][lr+64] = na1.w;
            Bs[nb][lk+0][lr]    = nb0.x; Bs[nb][lk+1][lr]    = nb0.y;
            Bs[nb][lk+2][lr]    = nb0.z; Bs[nb][lk+3][lr]    = nb0.w;
            Bs[nb][lk+0][lr+64] = nb1.x; Bs[nb][lk+1][lr+64] = nb1.y;
            Bs[nb][lk+2][lr+64] = nb1.z; Bs[nb][lk+3][lr+64] = nb1.w;
        }
        __syncthreads();
    }

    if (MODE == 2) {
        int8_t* C = (int8_t*)Cout;
#pragma unroll
        for (int i = 0; i < 8; i++) {
            size_t row = (size_t)(m0 + r0 + i) * N + n0 + c0;
            char4 p0, p1;
            p0.x = (acc[i][0] >= 0.f) ? 1 : -1;
            p0.y = (acc[i][1] >= 0.f) ? 1 : -1;
            p0.z = (acc[i][2] >= 0.f) ? 1 : -1;
            p0.w = (acc[i][3] >= 0.f) ? 1 : -1;
            p1.x = (acc[i][4] >= 0.f) ? 1 : -1;
            p1.y = (acc[i][5] >= 0.f) ? 1 : -1;
            p1.z = (acc[i][6] >= 0.f) ? 1 : -1;
            p1.w = (acc[i][7] >= 0.f) ? 1 : -1;
            *(char4*)&C[row]     = p0;
            *(char4*)&C[row + 4] = p1;
        }
    } else {
        float* C = (float*)Cout;
        const float s = (MODE == 1) ? QSCALE : 1.0f;
#pragma unroll
        for (int i = 0; i < 8; i++) {
            size_t row = (size_t)(m0 + r0 + i) * N + n0 + c0;
            float4 o0 = {tmp[i][0]*s, tmp[i][1]*s, tmp[i][2]*s, tmp[i][3]*s};
            float4 o1 = {tmp[i][4]*s, tmp[i][5]*s, tmp[i][6]*s, tmp[i][7]*s};
            *(float4*)&C[row]     = o0;
            *(float4*)&C[row + 4] = o1;
        }
    }
}

// ---------------------------------------------------------------------------
// Attention scan. One block per (b, h, e-half): 128 blocks, 256 threads.
// Per chunk (C=128): scores = q k^T (masked), cross = q @ state,
// out = cross + scores@v, state += k^T v.  k,v in {-1,+1} -> state exact
// integers in fp32 (|state| <= 4096 << 2^24).
// ---------------------------------------------------------------------------
struct AttSmem {
    float  qcT[128][132];      // q transposed: [d][c]
    float  scoresT[128][132];  // scores transposed: [j][i]
    float  state[128][68];     // [d][e], e-half (64 cols)
    int8_t kc[128][144];       // [c][d]
    int8_t kT[128][144];       // [d][c]
    int8_t vc[128][80];        // [c][e]  (64 e-cols of this half)
};

__device__ __forceinline__ void b4_to_f(unsigned w, float* f) {
    f[0] = (float)((int)(w << 24) >> 24);
    f[1] = (float)((int)(w << 16) >> 24);
    f[2] = (float)((int)(w <<  8) >> 24);
    f[3] = (float)((int) w        >> 24);
}

__global__ void __launch_bounds__(256)
att_kernel(const float* __restrict__ gq, const int8_t* __restrict__ gk,
           const int8_t* __restrict__ gv, float* __restrict__ gao,
           float* __restrict__ gstate, int write_state)
{
    extern __shared__ char sraw[];
    AttSmem& S = *(AttSmem*)sraw;

    const int pair = blockIdx.x;
    const int half = pair & 1;
    const int bh   = pair >> 1;
    const int b    = bh >> 4, h = bh & 15;
    const int tid  = threadIdx.x;

    for (int i = tid; i < 128 * 68; i += 256)
        ((float*)S.state)[i] = 0.f;

    const int ty = tid >> 4, tx = tid & 15;
    const int i0 = ty * 8, j0 = tx * 8, e0 = tx * 4;

    const size_t base_row = (size_t)b * SEQ;
    const int colq = h * DH;
    const int colv = h * DH + half * 64;

    const int lc = tid >> 1;            // 0..127 (row within chunk)
    const int dh = (tid & 1) * 64;      // 0 or 64

    for (int n = 0; n < 32; n++) {
        // ---- load chunk tiles ----
        {
            const size_t row = base_row + (size_t)n * 128 + lc;
            const float* qs = gq + row * DM + colq + dh;
#pragma unroll
            for (int d4 = 0; d4 < 64; d4 += 4) {
                float4 v = *(const float4*)(qs + d4);
                S.qcT[dh + d4 + 0][lc] = v.x;
                S.qcT[dh + d4 + 1][lc] = v.y;
                S.qcT[dh + d4 + 2][lc] = v.z;
                S.qcT[dh + d4 + 3][lc] = v.w;
            }
            const int8_t* ks = gk + row * DM + colq + dh;
#pragma unroll
            for (int d16 = 0; d16 < 64; d16 += 16) {
                int4 kw = *(const int4*)(ks + d16);
                *(int4*)&S.kc[lc][dh + d16] = kw;
                const int8_t* kb = (const int8_t*)&kw;
#pragma unroll
                for (int z = 0; z < 16; z++)
                    S.kT[dh + d16 + z][lc] = kb[z];
            }
            const int8_t* vs = gv + row * DM + colv + (dh >> 1);
            *(int4*)&S.vc[lc][(dh >> 1) + 0]  = *(const int4*)(vs);
            *(int4*)&S.vc[lc][(dh >> 1) + 16] = *(const int4*)(vs + 16);
        }
        __syncthreads();

        // ---- phase 2: scores(i0..+8, j0..+8) + cross(i0..+8, e0..+4) ----
        float sc[8][8], cr[8][4];
#pragma unroll
        for (int i = 0; i < 8; i++) {
#pragma unroll
            for (int j = 0; j < 8; j++) sc[i][j] = 0.f;
#pragma unroll
            for (int e = 0; e < 4; e++) cr[i][e] = 0.f;
        }
        for (int kk = 0; kk < 128; kk++) {
            float4 q0 = *(const float4*)&S.qcT[kk][i0];
            float4 q1 = *(const float4*)&S.qcT[kk][i0 + 4];
            float qv[8] = {q0.x, q0.y, q0.z, q0.w, q1.x, q1.y, q1.z, q1.w};
            uint2 kw = *(const uint2*)&S.kT[kk][j0];
            float kf[8];
            b4_to_f(kw.x, kf); b4_to_f(kw.y, kf + 4);
            float4 st = *(const float4*)&S.state[kk][e0];
            float sf[4] = {st.x, st.y, st.z, st.w};
#pragma unroll
            for (int i = 0; i < 8; i++) {
#pragma unroll
                for (int j = 0; j < 8; j++)
                    sc[i][j] = fmaf(qv[i], kf[j], sc[i][j]);
#pragma unroll
                for (int e = 0; e < 4; e++)
                    cr[i][e] = fmaf(qv[i], sf[e], cr[i][e]);
            }
        }
        // write masked scores transposed
#pragma unroll
        for (int jj = 0; jj < 8; jj++)
#pragma unroll
            for (int ii = 0; ii < 8; ii++) {
                int gi = i0 + ii, gj = j0 + jj;
                S.scoresT[gj][gi] = (gj <= gi) ? sc[ii][jj] : 0.f;
            }
        __syncthreads();

        // ---- phase 3: intra(i0..+8, e0..+4) + state update(d=i0..+8) ----
        float in8[8][4], up[8][4];
#pragma unroll
        for (int i = 0; i < 8; i++)
#pragma unroll
            for (int e = 0; e < 4; e++) { in8[i][e] = 0.f; up[i][e] = 0.f; }

        for (int kk = 0; kk < 128; kk++) {
            float4 s0 = *(const float4*)&S.scoresT[kk][i0];
            float4 s1 = *(const float4*)&S.scoresT[kk][i0 + 4];
            float sv[8] = {s0.x, s0.y, s0.z, s0.w, s1.x, s1.y, s1.z, s1.w};
            uint2 kw = *(const uint2*)&S.kc[kk][i0];
            float kf[8];
            b4_to_f(kw.x, kf); b4_to_f(kw.y, kf + 4);
            unsigned vw = *(const unsigned*)&S.vc[kk][e0];
            float vf[4];
            b4_to_f(vw, vf);
#pragma unroll
            for (int i = 0; i < 8; i++)
#pragma unroll
                for (int e = 0; e < 4; e++) {
                    in8[i][e] = fmaf(sv[i], vf[e], in8[i][e]);
                    up[i][e]  = fmaf(kf[i], vf[e], up[i][e]);
                }
        }
        // write out chunk + update state
#pragma unroll
        for (int ii = 0; ii < 8; ii++) {
            size_t row = (base_row + (size_t)n * 128 + i0 + ii) * DM + colv + e0;
            float4 o = {cr[ii][0] + in8[ii][0], cr[ii][1] + in8[ii][1],
                        cr[ii][2] + in8[ii][2], cr[ii][3] + in8[ii][3]};
            *(float4*)&gao[row] = o;
#pragma unroll
            for (int e = 0; e < 4; e++)
                S.state[i0 + ii][e0 + e] += up[ii][e];
        }
        __syncthreads();
    }

    if (write_state) {
        for (int idx = tid; idx < 128 * 64; idx += 256) {
            int d = idx >> 6, e = idx & 63;
            gstate[(((size_t)(b * NH + h) * DH) + d) * DH + half * 64 + e]
                = S.state[d][e];
        }
    }
}

// ---------------------------------------------------------------------------
extern "C" void kernel_launch(void* const* d_in, const int* in_sizes, int n_in,
                              void* d_out, int out_size)
{
    const float* x  = (const float*)d_in[0];
    const float* Wq = (const float*)d_in[1];
    const float* Wk = (const float*)d_in[2];
    const float* Wv = (const float*)d_in[3];
    const float* Wo = (const float*)d_in[4];
    float* out = (float*)d_out;

    void *pq, *pk, *pv, *pa;
    cudaGetSymbolAddress(&pq, g_q);
    cudaGetSymbolAddress(&pk, g_k);
    cudaGetSymbolAddress(&pv, g_v);
    cudaGetSymbolAddress(&pa, g_ao);

    dim3 grid(DM / 128, MROWS / 128), blk(256);
    gemm_nt<1><<<grid, blk>>>(x, Wq, pq);
    gemm_nt<2><<<grid, blk>>>(x, Wk, pk);
    gemm_nt<2><<<grid, blk>>>(x, Wv, pv);

    static int att_smem_set = 0;
    cudaFuncSetAttribute(att_kernel, cudaFuncAttributeMaxDynamicSharedMemorySize,
                         (int)sizeof(AttSmem));
    (void)att_smem_set;

    int write_state = ((size_t)out_size >= OUT_ELEMS + STATE_ELEMS) ? 1 : 0;
    att_kernel<<<128, 256, sizeof(AttSmem)>>>(
        (const float*)pq, (const int8_t*)pk, (const int8_t*)pv,
        (float*)pa, out + OUT_ELEMS, write_state);

    gemm_nt<0><<<grid, blk>>>((const float*)pa, Wo, out);
}

// round 6
// speedup vs baseline: 1.0938x; 1.0938x over previous
#include <cuda_runtime.h>
#include <cstdint>
#include <cstddef>

#define BSZ 4
#define SEQ 4096
#define DM  2048
#define NH  16
#define DH  128
#define MROWS (BSZ*SEQ)               // 16384
#define OUT_ELEMS ((size_t)MROWS*DM)  // 33554432
#define STATE_ELEMS ((size_t)BSZ*NH*DH*DH)
#define QSCALE 0.08838834764831845f   // 1/sqrt(128)

typedef unsigned long long u64;

// ---------------- scratch (device globals: allocation-free rule) ------------
__device__ float  g_q [(size_t)MROWS*DM];
__device__ int8_t g_k [(size_t)MROWS*DM];
__device__ int8_t g_v [(size_t)MROWS*DM];
__device__ float  g_ao[(size_t)MROWS*DM];

// ---------------- packed f32x2 helpers (per-lane IEEE fp32, rn) -------------
__device__ __forceinline__ u64 f2_dup(float x) {
    u64 r; asm("mov.b64 %0, {%1, %1};" : "=l"(r) : "f"(x)); return r;
}
__device__ __forceinline__ u64 f2_fma(u64 a, u64 b, u64 c) {
    u64 d; asm("fma.rn.f32x2 %0, %1, %2, %3;" : "=l"(d) : "l"(a), "l"(b), "l"(c));
    return d;
}
__device__ __forceinline__ u64 f2_add(u64 a, u64 b) {
    u64 d; asm("add.rn.f32x2 %0, %1, %2;" : "=l"(d) : "l"(a), "l"(b)); return d;
}
__device__ __forceinline__ float2 f2_unpack(u64 p) {
    float2 f; asm("mov.b64 {%0, %1}, %2;" : "=f"(f.x), "=f"(f.y) : "l"(p)); return f;
}

// ---------------------------------------------------------------------------
// GEMM (NT): C[m,n] = sum_k A[m,k]*B[n,k].  A:[16384,2048]  B:[2048,2048]
// 128x128 block tile, BK=16, 256 threads, 8x8 per thread, double buffered.
// Inner product uses packed fma.rn.f32x2 (FFMA2): accumulator pairs over
// adjacent rows (a-pairs read directly as 8B LDS), b broadcast into both
// lanes. Per-lane arithmetic is IEEE fp32 fma-rn -> results bit-identical
// to the scalar-FFMA version.
// MODE 0: plain fp32 out.  MODE 1: fp32 out * QSCALE.
// MODE 2: sign epilogue -> int8, two-level fp32 accumulation (flush every
//         4 k-tiles = 64 terms) -> pre-sign rms error ~2.4e-7.
// ---------------------------------------------------------------------------
template<int MODE>
__global__ void __launch_bounds__(256)
gemm_nt(const float* __restrict__ A, const float* __restrict__ B,
        void* __restrict__ Cout)
{
    constexpr int K = DM, N = DM, BK = 16, NT = K / BK;
    __shared__ float As[2][BK][132];
    __shared__ float Bs[2][BK][132];

    const int tid = threadIdx.x;
    const int m0 = blockIdx.y * 128, n0 = blockIdx.x * 128;
    const int lr = tid >> 2;            // 0..63
    const int lk = (tid & 3) << 2;      // 0,4,8,12

    const float* Ag  = A + (size_t)(m0 + lr) * K + lk;
    const float* Ag2 = Ag + (size_t)64 * K;
    const float* Bg  = B + (size_t)(n0 + lr) * K + lk;
    const float* Bg2 = Bg + (size_t)64 * K;

    // prologue: tile 0
    {
        float4 a0 = *(const float4*)(Ag);
        float4 a1 = *(const float4*)(Ag2);
        float4 b0 = *(const float4*)(Bg);
        float4 b1 = *(const float4*)(Bg2);
        As[0][lk+0][lr]    = a0.x; As[0][lk+1][lr]    = a0.y;
        As[0][lk+2][lr]    = a0.z; As[0][lk+3][lr]    = a0.w;
        As[0][lk+0][lr+64] = a1.x; As[0][lk+1][lr+64] = a1.y;
        As[0][lk+2][lr+64] = a1.z; As[0][lk+3][lr+64] = a1.w;
        Bs[0][lk+0][lr]    = b0.x; Bs[0][lk+1][lr]    = b0.y;
        Bs[0][lk+2][lr]    = b0.z; Bs[0][lk+3][lr]    = b0.w;
        Bs[0][lk+0][lr+64] = b1.x; Bs[0][lk+1][lr+64] = b1.y;
        Bs[0][lk+2][lr+64] = b1.z; Bs[0][lk+3][lr+64] = b1.w;
    }
    __syncthreads();

    const int ty = tid >> 4, tx = tid & 15;
    const int r0 = ty * 8, c0 = tx * 8;

    // packed accumulators: [row-pair 0..3][col 0..7]; lane .x = even row
    u64 t2[4][8];     // segment partial (MODE 2) or full accumulator (0/1)
    u64 a2[4][8];     // long accumulator (MODE 2 only)
#pragma unroll
    for (int ip = 0; ip < 4; ip++)
#pragma unroll
        for (int j = 0; j < 8; j++) {
            t2[ip][j] = 0ull;
            if (MODE == 2) a2[ip][j] = 0ull;
        }

    for (int t = 0; t < NT; t++) {
        const int cur = t & 1;
        float4 na0, na1, nb0, nb1;
        const bool more = (t + 1 < NT);
        if (more) {
            const int off = (t + 1) * BK;
            na0 = *(const float4*)(Ag  + off);
            na1 = *(const float4*)(Ag2 + off);
            nb0 = *(const float4*)(Bg  + off);
            nb1 = *(const float4*)(Bg2 + off);
        }
#pragma unroll
        for (int kk = 0; kk < BK; kk++) {
            // a-pairs: adjacent rows, read directly as 8B from SMEM
            u64 ap0 = *(const u64*)&As[cur][kk][r0 + 0];
            u64 ap1 = *(const u64*)&As[cur][kk][r0 + 2];
            u64 ap2 = *(const u64*)&As[cur][kk][r0 + 4];
            u64 ap3 = *(const u64*)&As[cur][kk][r0 + 6];
            float4 y0 = *(const float4*)&Bs[cur][kk][c0];
            float4 y1 = *(const float4*)&Bs[cur][kk][c0 + 4];
            u64 bd[8];
            bd[0] = f2_dup(y0.x); bd[1] = f2_dup(y0.y);
            bd[2] = f2_dup(y0.z); bd[3] = f2_dup(y0.w);
            bd[4] = f2_dup(y1.x); bd[5] = f2_dup(y1.y);
            bd[6] = f2_dup(y1.z); bd[7] = f2_dup(y1.w);
#pragma unroll
            for (int j = 0; j < 8; j++) {
                t2[0][j] = f2_fma(ap0, bd[j], t2[0][j]);
                t2[1][j] = f2_fma(ap1, bd[j], t2[1][j]);
                t2[2][j] = f2_fma(ap2, bd[j], t2[2][j]);
                t2[3][j] = f2_fma(ap3, bd[j], t2[3][j]);
            }
        }
        if (MODE == 2) {
            if ((t & 3) == 3) {   // flush every 64 k-terms (includes t=127)
#pragma unroll
                for (int ip = 0; ip < 4; ip++)
#pragma unroll
                    for (int j = 0; j < 8; j++) {
                        a2[ip][j] = f2_add(a2[ip][j], t2[ip][j]);
                        t2[ip][j] = 0ull;
                    }
            }
        }
        if (more) {
            const int nb = cur ^ 1;
            As[nb][lk+0][lr]    = na0.x; As[nb][lk+1][lr]    = na0.y;
            As[nb][lk+2][lr]    = na0.z; As[nb][lk+3][lr]    = na0.w;
            As[nb][lk+0][lr+64] = na1.x; As[nb][lk+1][lr+64] = na1.y;
            As[nb][lk+2][lr+64] = na1.z; As[nb][lk+3][lr+64] = na1.w;
            Bs[nb][lk+0][lr]    = nb0.x; Bs[nb][lk+1][lr]    = nb0.y;
            Bs[nb][lk+2][lr]    = nb0.z; Bs[nb][lk+3][lr]    = nb0.w;
            Bs[nb][lk+0][lr+64] = nb1.x; Bs[nb][lk+1][lr+64] = nb1.y;
            Bs[nb][lk+2][lr+64] = nb1.z; Bs[nb][lk+3][lr+64] = nb1.w;
        }
        __syncthreads();
    }

    if (MODE == 2) {
        int8_t* C = (int8_t*)Cout;
#pragma unroll
        for (int ip = 0; ip < 4; ip++) {
            float2 v[8];
#pragma unroll
            for (int j = 0; j < 8; j++) v[j] = f2_unpack(a2[ip][j]);
            size_t row0 = (size_t)(m0 + r0 + 2*ip) * N + n0 + c0;
            size_t row1 = row0 + N;
            char4 p0, p1;
            p0.x = (v[0].x >= 0.f) ? 1 : -1; p0.y = (v[1].x >= 0.f) ? 1 : -1;
            p0.z = (v[2].x >= 0.f) ? 1 : -1; p0.w = (v[3].x >= 0.f) ? 1 : -1;
            p1.x = (v[4].x >= 0.f) ? 1 : -1; p1.y = (v[5].x >= 0.f) ? 1 : -1;
            p1.z = (v[6].x >= 0.f) ? 1 : -1; p1.w = (v[7].x >= 0.f) ? 1 : -1;
            *(char4*)&C[row0]     = p0;
            *(char4*)&C[row0 + 4] = p1;
            p0.x = (v[0].y >= 0.f) ? 1 : -1; p0.y = (v[1].y >= 0.f) ? 1 : -1;
            p0.z = (v[2].y >= 0.f) ? 1 : -1; p0.w = (v[3].y >= 0.f) ? 1 : -1;
            p1.x = (v[4].y >= 0.f) ? 1 : -1; p1.y = (v[5].y >= 0.f) ? 1 : -1;
            p1.z = (v[6].y >= 0.f) ? 1 : -1; p1.w = (v[7].y >= 0.f) ? 1 : -1;
            *(char4*)&C[row1]     = p0;
            *(char4*)&C[row1 + 4] = p1;
        }
    } else {
        float* C = (float*)Cout;
        const float s = (MODE == 1) ? QSCALE : 1.0f;
#pragma unroll
        for (int ip = 0; ip < 4; ip++) {
            float2 v[8];
#pragma unroll
            for (int j = 0; j < 8; j++) v[j] = f2_unpack(t2[ip][j]);
            size_t row0 = (size_t)(m0 + r0 + 2*ip) * N + n0 + c0;
            size_t row1 = row0 + N;
            float4 o;
            o.x = v[0].x*s; o.y = v[1].x*s; o.z = v[2].x*s; o.w = v[3].x*s;
            *(float4*)&C[row0] = o;
            o.x = v[4].x*s; o.y = v[5].x*s; o.z = v[6].x*s; o.w = v[7].x*s;
            *(float4*)&C[row0 + 4] = o;
            o.x = v[0].y*s; o.y = v[1].y*s; o.z = v[2].y*s; o.w = v[3].y*s;
            *(float4*)&C[row1] = o;
            o.x = v[4].y*s; o.y = v[5].y*s; o.z = v[6].y*s; o.w = v[7].y*s;
            *(float4*)&C[row1 + 4] = o;
        }
    }
}

// ---------------------------------------------------------------------------
// Attention scan. One block per (b, h, e-half): 128 blocks, 256 threads.
// Per chunk (C=128): scores = q k^T (masked), cross = q @ state,
// out = cross + scores@v, state += k^T v.  k,v in {-1,+1} -> state exact
// integers in fp32 (|state| <= 4096 << 2^24).  (Unchanged from R4.)
// ---------------------------------------------------------------------------
struct AttSmem {
    float  qcT[128][132];      // q transposed: [d][c]
    float  scoresT[128][132];  // scores transposed: [j][i]
    float  state[128][68];     // [d][e], e-half (64 cols)
    int8_t kc[128][144];       // [c][d]
    int8_t kT[128][144];       // [d][c]
    int8_t vc[128][80];        // [c][e]  (64 e-cols of this half)
};

__device__ __forceinline__ void b4_to_f(unsigned w, float* f) {
    f[0] = (float)((int)(w << 24) >> 24);
    f[1] = (float)((int)(w << 16) >> 24);
    f[2] = (float)((int)(w <<  8) >> 24);
    f[3] = (float)((int) w        >> 24);
}

__global__ void __launch_bounds__(256)
att_kernel(const float* __restrict__ gq, const int8_t* __restrict__ gk,
           const int8_t* __restrict__ gv, float* __restrict__ gao,
           float* __restrict__ gstate, int write_state)
{
    extern __shared__ char sraw[];
    AttSmem& S = *(AttSmem*)sraw;

    const int pair = blockIdx.x;
    const int half = pair & 1;
    const int bh   = pair >> 1;
    const int b    = bh >> 4, h = bh & 15;
    const int tid  = threadIdx.x;

    for (int i = tid; i < 128 * 68; i += 256)
        ((float*)S.state)[i] = 0.f;

    const int ty = tid >> 4, tx = tid & 15;
    const int i0 = ty * 8, j0 = tx * 8, e0 = tx * 4;

    const size_t base_row = (size_t)b * SEQ;
    const int colq = h * DH;
    const int colv = h * DH + half * 64;

    const int lc = tid >> 1;            // 0..127 (row within chunk)
    const int dh = (tid & 1) * 64;      // 0 or 64

    for (int n = 0; n < 32; n++) {
        // ---- load chunk tiles ----
        {
            const size_t row = base_row + (size_t)n * 128 + lc;
            const float* qs = gq + row * DM + colq + dh;
#pragma unroll
            for (int d4 = 0; d4 < 64; d4 += 4) {
                float4 v = *(const float4*)(qs + d4);
                S.qcT[dh + d4 + 0][lc] = v.x;
                S.qcT[dh + d4 + 1][lc] = v.y;
                S.qcT[dh + d4 + 2][lc] = v.z;
                S.qcT[dh + d4 + 3][lc] = v.w;
            }
            const int8_t* ks = gk + row * DM + colq + dh;
#pragma unroll
            for (int d16 = 0; d16 < 64; d16 += 16) {
                int4 kw = *(const int4*)(ks + d16);
                *(int4*)&S.kc[lc][dh + d16] = kw;
                const int8_t* kb = (const int8_t*)&kw;
#pragma unroll
                for (int z = 0; z < 16; z++)
                    S.kT[dh + d16 + z][lc] = kb[z];
            }
            const int8_t* vs = gv + row * DM + colv + (dh >> 1);
            *(int4*)&S.vc[lc][(dh >> 1) + 0]  = *(const int4*)(vs);
            *(int4*)&S.vc[lc][(dh >> 1) + 16] = *(const int4*)(vs + 16);
        }
        __syncthreads();

        // ---- phase 2: scores(i0..+8, j0..+8) + cross(i0..+8, e0..+4) ----
        float sc[8][8], cr[8][4];
#pragma unroll
        for (int i = 0; i < 8; i++) {
#pragma unroll
            for (int j = 0; j < 8; j++) sc[i][j] = 0.f;
#pragma unroll
            for (int e = 0; e < 4; e++) cr[i][e] = 0.f;
        }
        for (int kk = 0; kk < 128; kk++) {
            float4 q0 = *(const float4*)&S.qcT[kk][i0];
            float4 q1 = *(const float4*)&S.qcT[kk][i0 + 4];
            float qv[8] = {q0.x, q0.y, q0.z, q0.w, q1.x, q1.y, q1.z, q1.w};
            uint2 kw = *(const uint2*)&S.kT[kk][j0];
            float kf[8];
            b4_to_f(kw.x, kf); b4_to_f(kw.y, kf + 4);
            float4 st = *(const float4*)&S.state[kk][e0];
            float sf[4] = {st.x, st.y, st.z, st.w};
#pragma unroll
            for (int i = 0; i < 8; i++) {
#pragma unroll
                for (int j = 0; j < 8; j++)
                    sc[i][j] = fmaf(qv[i], kf[j], sc[i][j]);
#pragma unroll
                for (int e = 0; e < 4; e++)
                    cr[i][e] = fmaf(qv[i], sf[e], cr[i][e]);
            }
        }
        // write masked scores transposed
#pragma unroll
        for (int jj = 0; jj < 8; jj++)
#pragma unroll
            for (int ii = 0; ii < 8; ii++) {
                int gi = i0 + ii, gj = j0 + jj;
                S.scoresT[gj][gi] = (gj <= gi) ? sc[ii][jj] : 0.f;
            }
        __syncthreads();

        // ---- phase 3: intra(i0..+8, e0..+4) + state update(d=i0..+8) ----
        float in8[8][4], up[8][4];
#pragma unroll
        for (int i = 0; i < 8; i++)
#pragma unroll
            for (int e = 0; e < 4; e++) { in8[i][e] = 0.f; up[i][e] = 0.f; }

        for (int kk = 0; kk < 128; kk++) {
            float4 s0 = *(const float4*)&S.scoresT[kk][i0];
            float4 s1 = *(const float4*)&S.scoresT[kk][i0 + 4];
            float sv[8] = {s0.x, s0.y, s0.z, s0.w, s1.x, s1.y, s1.z, s1.w};
            uint2 kw = *(const uint2*)&S.kc[kk][i0];
            float kf[8];
            b4_to_f(kw.x, kf); b4_to_f(kw.y, kf + 4);
            unsigned vw = *(const unsigned*)&S.vc[kk][e0];
            float vf[4];
            b4_to_f(vw, vf);
#pragma unroll
            for (int i = 0; i < 8; i++)
#pragma unroll
                for (int e = 0; e < 4; e++) {
                    in8[i][e] = fmaf(sv[i], vf[e], in8[i][e]);
                    up[i][e]  = fmaf(kf[i], vf[e], up[i][e]);
                }
        }
        // write out chunk + update state
#pragma unroll
        for (int ii = 0; ii < 8; ii++) {
            size_t row = (base_row + (size_t)n * 128 + i0 + ii) * DM + colv + e0;
            float4 o = {cr[ii][0] + in8[ii][0], cr[ii][1] + in8[ii][1],
                        cr[ii][2] + in8[ii][2], cr[ii][3] + in8[ii][3]};
            *(float4*)&gao[row] = o;
#pragma unroll
            for (int e = 0; e < 4; e++)
                S.state[i0 + ii][e0 + e] += up[ii][e];
        }
        __syncthreads();
    }

    if (write_state) {
        for (int idx = tid; idx < 128 * 64; idx += 256) {
            int d = idx >> 6, e = idx & 63;
            gstate[(((size_t)(b * NH + h) * DH) + d) * DH + half * 64 + e]
                = S.state[d][e];
        }
    }
}

// ---------------------------------------------------------------------------
extern "C" void kernel_launch(void* const* d_in, const int* in_sizes, int n_in,
                              void* d_out, int out_size)
{
    const float* x  = (const float*)d_in[0];
    const float* Wq = (const float*)d_in[1];
    const float* Wk = (const float*)d_in[2];
    const float* Wv = (const float*)d_in[3];
    const float* Wo = (const float*)d_in[4];
    float* out = (float*)d_out;

    void *pq, *pk, *pv, *pa;
    cudaGetSymbolAddress(&pq, g_q);
    cudaGetSymbolAddress(&pk, g_k);
    cudaGetSymbolAddress(&pv, g_v);
    cudaGetSymbolAddress(&pa, g_ao);

    dim3 grid(DM / 128, MROWS / 128), blk(256);
    gemm_nt<1><<<grid, blk>>>(x, Wq, pq);
    gemm_nt<2><<<grid, blk>>>(x, Wk, pk);
    gemm_nt<2><<<grid, blk>>>(x, Wv, pv);

    cudaFuncSetAttribute(att_kernel, cudaFuncAttributeMaxDynamicSharedMemorySize,
                         (int)sizeof(AttSmem));
    int write_state = ((size_t)out_size >= OUT_ELEMS + STATE_ELEMS) ? 1 : 0;
    att_kernel<<<128, 256, sizeof(AttSmem)>>>(
        (const float*)pq, (const int8_t*)pk, (const int8_t*)pv,
        (float*)pa, out + OUT_ELEMS, write_state);

    gemm_nt<0><<<grid, blk>>>((const float*)pa, Wo, out);
}

// round 8
// speedup vs baseline: 1.4160x; 1.2946x over previous
#include <cuda_runtime.h>
#include <cuda_bf16.h>
#include <cstdint>
#include <cstddef>

#define BSZ 4
#define SEQ 4096
#define DM  2048
#define NH  16
#define DH  128
#define MROWS (BSZ*SEQ)               // 16384
#define OUT_ELEMS ((size_t)MROWS*DM)  // 33554432
#define STATE_ELEMS ((size_t)BSZ*NH*DH*DH)
#define QSCALE 0.08838834764831845f   // 1/sqrt(128)

typedef unsigned long long u64;

// ---------------- scratch (device globals: allocation-free rule) ------------
__device__ float  g_q [(size_t)MROWS*DM];
__device__ int8_t g_k [(size_t)MROWS*DM];
__device__ int8_t g_v [(size_t)MROWS*DM];
__device__ float  g_ao[(size_t)MROWS*DM];
// bf16 2-split buffers
__device__ __nv_bfloat16 g_x1[(size_t)MROWS*DM];
__device__ __nv_bfloat16 g_x2[(size_t)MROWS*DM];
__device__ __nv_bfloat16 g_a1[(size_t)MROWS*DM];
__device__ __nv_bfloat16 g_a2[(size_t)MROWS*DM];
__device__ __nv_bfloat16 g_wq1[(size_t)DM*DM];
__device__ __nv_bfloat16 g_wq2[(size_t)DM*DM];
__device__ __nv_bfloat16 g_wo1[(size_t)DM*DM];
__device__ __nv_bfloat16 g_wo2[(size_t)DM*DM];

// ---------------- packed f32x2 helpers (per-lane IEEE fp32, rn) -------------
__device__ __forceinline__ u64 f2_dup(float x) {
    u64 r; asm("mov.b64 %0, {%1, %1};" : "=l"(r) : "f"(x)); return r;
}
__device__ __forceinline__ u64 f2_fma(u64 a, u64 b, u64 c) {
    u64 d; asm("fma.rn.f32x2 %0, %1, %2, %3;" : "=l"(d) : "l"(a), "l"(b), "l"(c));
    return d;
}
__device__ __forceinline__ u64 f2_add(u64 a, u64 b) {
    u64 d; asm("add.rn.f32x2 %0, %1, %2;" : "=l"(d) : "l"(a), "l"(b)); return d;
}
__device__ __forceinline__ float2 f2_unpack(u64 p) {
    float2 f; asm("mov.b64 {%0, %1}, %2;" : "=f"(f.x), "=f"(f.y) : "l"(p)); return f;
}

// ---------------- mma.sync / ldmatrix / cp.async helpers (arch-neutral) -----
__device__ __forceinline__ uint32_t smem_u32(const void* p) {
    uint32_t a;
    asm("{ .reg .u64 t; cvta.to.shared.u64 t, %1; cvt.u32.u64 %0, t; }"
        : "=r"(a) : "l"(p));
    return a;
}
__device__ __forceinline__ void ldsm4(uint32_t* r, uint32_t addr) {
    asm volatile("ldmatrix.sync.aligned.m8n8.x4.shared.b16 {%0,%1,%2,%3}, [%4];"
        : "=r"(r[0]), "=r"(r[1]), "=r"(r[2]), "=r"(r[3]) : "r"(addr));
}
__device__ __forceinline__ void mma_bf16(float* c, const uint32_t* a,
                                         const uint32_t* b) {
    asm volatile(
        "mma.sync.aligned.m16n8k16.row.col.f32.bf16.bf16.f32 "
        "{%0,%1,%2,%3}, {%4,%5,%6,%7}, {%8,%9}, {%0,%1,%2,%3};"
        : "+f"(c[0]), "+f"(c[1]), "+f"(c[2]), "+f"(c[3])
        : "r"(a[0]), "r"(a[1]), "r"(a[2]), "r"(a[3]), "r"(b[0]), "r"(b[1]));
}
#define CPA(dst, src) asm volatile("cp.async.cg.shared.global [%0], [%1], 16;" :: "r"(dst), "l"(src))
#define CPC()         asm volatile("cp.async.commit_group;")
#define CPW0()        asm volatile("cp.async.wait_group 0;")

// ---------------------------------------------------------------------------
// split: fp32 -> bf16 hi + bf16 lo  (x = hi + lo + O(2^-18 x))
// ---------------------------------------------------------------------------
__global__ void split_bf16(const float* __restrict__ s, size_t n,
                           __nv_bfloat16* __restrict__ hi,
                           __nv_bfloat16* __restrict__ lo)
{
    size_t stride = (size_t)gridDim.x * blockDim.x * 4;
    for (size_t i = ((size_t)blockIdx.x * blockDim.x + threadIdx.x) * 4;
         i < n; i += stride) {
        float4 v = *(const float4*)(s + i);
        __nv_bfloat16 hx = __float2bfloat16(v.x);
        __nv_bfloat16 hy = __float2bfloat16(v.y);
        __nv_bfloat16 hz = __float2bfloat16(v.z);
        __nv_bfloat16 hw = __float2bfloat16(v.w);
        __nv_bfloat16 lx = __float2bfloat16(v.x - __bfloat162float(hx));
        __nv_bfloat16 ly = __float2bfloat16(v.y - __bfloat162float(hy));
        __nv_bfloat16 lz = __float2bfloat16(v.z - __bfloat162float(hz));
        __nv_bfloat16 lw = __float2bfloat16(v.w - __bfloat162float(hw));
        *(__nv_bfloat162*)(hi + i)     = __nv_bfloat162(hx, hy);
        *(__nv_bfloat162*)(hi + i + 2) = __nv_bfloat162(hz, hw);
        *(__nv_bfloat162*)(lo + i)     = __nv_bfloat162(lx, ly);
        *(__nv_bfloat162*)(lo + i + 2) = __nv_bfloat162(lz, lw);
    }
}

// ---------------------------------------------------------------------------
// Tensor-core (mma.sync) 2-split bf16 GEMM (NT): C[m,n] = sum_k A[m,k]*B[n,k]
//   via A1B1 + A1B2 + A2B1, fp32 register accumulators.
// Tile 128x128, BK=32, 256 threads (8 warps, warp tile 32x64), cp.async
// double-buffered SMEM (4 tiles x 10240B per buffer).
// MODE 0: plain fp32 out.  MODE 1: fp32 out * QSCALE.
// ---------------------------------------------------------------------------
#define RS   40                        // SMEM row stride in bf16 (80 bytes)
#define TILE_B (128 * RS * 2)          // 10240 bytes per tile
#define BUF_B  (4 * TILE_B)            // 40960 bytes per stage buffer
#define MMA_SMEM (2 * BUF_B)           // 81920

template<int MODE>
__global__ void __launch_bounds__(256, 1)
mmah_gemm(const __nv_bfloat16* __restrict__ A1, const __nv_bfloat16* __restrict__ A2,
          const __nv_bfloat16* __restrict__ B1, const __nv_bfloat16* __restrict__ B2,
          float* __restrict__ C)
{
    extern __shared__ char sm[];
    const uint32_t smb = smem_u32(sm);
    const int tid = threadIdx.x, lane = tid & 31, w = tid >> 5;
    const int m0 = blockIdx.y * 128, n0 = blockIdx.x * 128;
    const int wm = (w & 3) * 32, wn = (w >> 2) * 64;

    const __nv_bfloat16* src[4] = {A1, A2, B1, B2};
    const int rbs[4] = {m0, m0, n0, n0};
    constexpr int NT = DM / 32;   // 64 stages

    // per-thread copy geometry: 512 16B-chunks per tile, 2 per thread
    // chunk c: row = c>>2, col8 = (c&3)*8 (bf16 units)
    auto issue = [&](int t) {
        const uint32_t bb = smb + (uint32_t)(t & 1) * BUF_B;
        const int k0 = t * 32;
#pragma unroll
        for (int i = 0; i < 2; i++) {
            const int c = tid + 256 * i;
            const int row = c >> 2, col8 = (c & 3) * 8;
#pragma unroll
            for (int X = 0; X < 4; X++) {
                uint32_t dst = bb + (uint32_t)X * TILE_B + row * (RS * 2) + col8 * 2;
                const __nv_bfloat16* s = src[X] + (size_t)(rbs[X] + row) * DM + k0 + col8;
                CPA(dst, s);
            }
        }
    };

    float acc[2][8][4];
#pragma unroll
    for (int mt = 0; mt < 2; mt++)
#pragma unroll
        for (int nt = 0; nt < 8; nt++)
#pragma unroll
            for (int e = 0; e < 4; e++) acc[mt][nt][e] = 0.f;

    issue(0); CPC();

    const int arow = wm + (lane & 15);
    const uint32_t acolo = ((lane >> 4) << 3) * 2;           // bytes
    const int brow = wn + (lane & 7) + ((lane >> 4) << 3);
    const uint32_t bcolo = (((lane >> 3) & 1) << 3) * 2;     // bytes

    for (int t = 0; t < NT; t++) {
        CPW0();
        __syncthreads();
        if (t + 1 < NT) { issue(t + 1); CPC(); }

        const uint32_t bb = smb + (uint32_t)(t & 1) * BUF_B;
#pragma unroll
        for (int ks = 0; ks < 32; ks += 16) {
            const uint32_t ko = (uint32_t)ks * 2;
            uint32_t a1f[2][4], a2f[2][4], b1f[8][2], b2f[8][2];
            // A fragments (non-trans ldmatrix, rows = m, cols = k)
            ldsm4(a1f[0], bb + 0*TILE_B + (arow     ) * (RS*2) + ko + acolo);
            ldsm4(a1f[1], bb + 0*TILE_B + (arow + 16) * (RS*2) + ko + acolo);
            ldsm4(a2f[0], bb + 1*TILE_B + (arow     ) * (RS*2) + ko + acolo);
            ldsm4(a2f[1], bb + 1*TILE_B + (arow + 16) * (RS*2) + ko + acolo);
            // B fragments (non-trans ldmatrix, rows = n, cols = k)
#pragma unroll
            for (int np = 0; np < 4; np++) {
                uint32_t r[4];
                ldsm4(r, bb + 2*TILE_B + (brow + np*16) * (RS*2) + ko + bcolo);
                b1f[np*2][0] = r[0]; b1f[np*2][1] = r[1];
                b1f[np*2+1][0] = r[2]; b1f[np*2+1][1] = r[3];
                ldsm4(r, bb + 3*TILE_B + (brow + np*16) * (RS*2) + ko + bcolo);
                b2f[np*2][0] = r[0]; b2f[np*2][1] = r[1];
                b2f[np*2+1][0] = r[2]; b2f[np*2+1][1] = r[3];
            }
#pragma unroll
            for (int mt = 0; mt < 2; mt++)
#pragma unroll
                for (int nt = 0; nt < 8; nt++) {
                    mma_bf16(acc[mt][nt], a1f[mt], b1f[nt]);
                    mma_bf16(acc[mt][nt], a1f[mt], b2f[nt]);
                    mma_bf16(acc[mt][nt], a2f[mt], b1f[nt]);
                }
        }
        __syncthreads();
    }

    // epilogue: C frag (m = lane/4 (+8), n = 2*(lane%4)+{0,1})
    const float s = (MODE == 1) ? QSCALE : 1.0f;
#pragma unroll
    for (int mt = 0; mt < 2; mt++)
#pragma unroll
        for (int nt = 0; nt < 8; nt++) {
            const int m = m0 + wm + mt * 16 + (lane >> 2);
            const int n = n0 + wn + nt * 8 + 2 * (lane & 3);
            float2 o0 = {acc[mt][nt][0] * s, acc[mt][nt][1] * s};
            float2 o1 = {acc[mt][nt][2] * s, acc[mt][nt][3] * s};
            *(float2*)&C[(size_t)m * DM + n]       = o0;
            *(float2*)&C[(size_t)(m + 8) * DM + n] = o1;
        }
}

// ---------------------------------------------------------------------------
// fp32 FFMA2 GEMM (NT) — K/V sign projections only (MODE 2). Bit-identical
// to the R5-validated path.
// ---------------------------------------------------------------------------
template<int MODE>
__global__ void __launch_bounds__(256)
gemm_nt(const float* __restrict__ A, const float* __restrict__ B,
        void* __restrict__ Cout)
{
    constexpr int K = DM, N = DM, BK = 16, NT = K / BK;
    __shared__ float As[2][BK][132];
    __shared__ float Bs[2][BK][132];

    const int tid = threadIdx.x;
    const int m0 = blockIdx.y * 128, n0 = blockIdx.x * 128;
    const int lr = tid >> 2;
    const int lk = (tid & 3) << 2;

    const float* Ag  = A + (size_t)(m0 + lr) * K + lk;
    const float* Ag2 = Ag + (size_t)64 * K;
    const float* Bg  = B + (size_t)(n0 + lr) * K + lk;
    const float* Bg2 = Bg + (size_t)64 * K;

    {
        float4 a0 = *(const float4*)(Ag);
        float4 a1 = *(const float4*)(Ag2);
        float4 b0 = *(const float4*)(Bg);
        float4 b1 = *(const float4*)(Bg2);
        As[0][lk+0][lr]    = a0.x; As[0][lk+1][lr]    = a0.y;
        As[0][lk+2][lr]    = a0.z; As[0][lk+3][lr]    = a0.w;
        As[0][lk+0][lr+64] = a1.x; As[0][lk+1][lr+64] = a1.y;
        As[0][lk+2][lr+64] = a1.z; As[0][lk+3][lr+64] = a1.w;
        Bs[0][lk+0][lr]    = b0.x; Bs[0][lk+1][lr]    = b0.y;
        Bs[0][lk+2][lr]    = b0.z; Bs[0][lk+3][lr]    = b0.w;
        Bs[0][lk+0][lr+64] = b1.x; Bs[0][lk+1][lr+64] = b1.y;
        Bs[0][lk+2][lr+64] = b1.z; Bs[0][lk+3][lr+64] = b1.w;
    }
    __syncthreads();

    const int ty = tid >> 4, tx = tid & 15;
    const int r0 = ty * 8, c0 = tx * 8;

    u64 t2[4][8];
    u64 a2[4][8];
#pragma unroll
    for (int ip = 0; ip < 4; ip++)
#pragma unroll
        for (int j = 0; j < 8; j++) {
            t2[ip][j] = 0ull;
            if (MODE == 2) a2[ip][j] = 0ull;
        }

    for (int t = 0; t < NT; t++) {
        const int cur = t & 1;
        float4 na0, na1, nb0, nb1;
        const bool more = (t + 1 < NT);
        if (more) {
            const int off = (t + 1) * BK;
            na0 = *(const float4*)(Ag  + off);
            na1 = *(const float4*)(Ag2 + off);
            nb0 = *(const float4*)(Bg  + off);
            nb1 = *(const float4*)(Bg2 + off);
        }
#pragma unroll
        for (int kk = 0; kk < BK; kk++) {
            u64 ap0 = *(const u64*)&As[cur][kk][r0 + 0];
            u64 ap1 = *(const u64*)&As[cur][kk][r0 + 2];
            u64 ap2 = *(const u64*)&As[cur][kk][r0 + 4];
            u64 ap3 = *(const u64*)&As[cur][kk][r0 + 6];
            float4 y0 = *(const float4*)&Bs[cur][kk][c0];
            float4 y1 = *(const float4*)&Bs[cur][kk][c0 + 4];
            u64 bd[8];
            bd[0] = f2_dup(y0.x); bd[1] = f2_dup(y0.y);
            bd[2] = f2_dup(y0.z); bd[3] = f2_dup(y0.w);
            bd[4] = f2_dup(y1.x); bd[5] = f2_dup(y1.y);
            bd[6] = f2_dup(y1.z); bd[7] = f2_dup(y1.w);
#pragma unroll
            for (int j = 0; j < 8; j++) {
                t2[0][j] = f2_fma(ap0, bd[j], t2[0][j]);
                t2[1][j] = f2_fma(ap1, bd[j], t2[1][j]);
                t2[2][j] = f2_fma(ap2, bd[j], t2[2][j]);
                t2[3][j] = f2_fma(ap3, bd[j], t2[3][j]);
            }
        }
        if (MODE == 2) {
            if ((t & 3) == 3) {
#pragma unroll
                for (int ip = 0; ip < 4; ip++)
#pragma unroll
                    for (int j = 0; j < 8; j++) {
                        a2[ip][j] = f2_add(a2[ip][j], t2[ip][j]);
                        t2[ip][j] = 0ull;
                    }
            }
        }
        if (more) {
            const int nb = cur ^ 1;
            As[nb][lk+0][lr]    = na0.x; As[nb][lk+1][lr]    = na0.y;
            As[nb][lk+2][lr]    = na0.z; As[nb][lk+3][lr]    = na0.w;
            As[nb][lk+0][lr+64] = na1.x; As[nb][lk+1][lr+64] = na1.y;
            As[nb][lk+2][lr+64] = na1.z; As[nb][lk+3][lr+64] = na1.w;
            Bs[nb][lk+0][lr]    = nb0.x; Bs[nb][lk+1][lr]    = nb0.y;
            Bs[nb][lk+2][lr]    = nb0.z; Bs[nb][lk+3][lr]    = nb0.w;
            Bs[nb][lk+0][lr+64] = nb1.x; Bs[nb][lk+1][lr+64] = nb1.y;
            Bs[nb][lk+2][lr+64] = nb1.z; Bs[nb][lk+3][lr+64] = nb1.w;
        }
        __syncthreads();
    }

    if (MODE == 2) {
        int8_t* Cc = (int8_t*)Cout;
#pragma unroll
        for (int ip = 0; ip < 4; ip++) {
            float2 v[8];
#pragma unroll
            for (int j = 0; j < 8; j++) v[j] = f2_unpack(a2[ip][j]);
            size_t row0 = (size_t)(m0 + r0 + 2*ip) * N + n0 + c0;
            size_t row1 = row0 + N;
            char4 p0, p1;
            p0.x = (v[0].x >= 0.f) ? 1 : -1; p0.y = (v[1].x >= 0.f) ? 1 : -1;
            p0.z = (v[2].x >= 0.f) ? 1 : -1; p0.w = (v[3].x >= 0.f) ? 1 : -1;
            p1.x = (v[4].x >= 0.f) ? 1 : -1; p1.y = (v[5].x >= 0.f) ? 1 : -1;
            p1.z = (v[6].x >= 0.f) ? 1 : -1; p1.w = (v[7].x >= 0.f) ? 1 : -1;
            *(char4*)&Cc[row0]     = p0;
            *(char4*)&Cc[row0 + 4] = p1;
            p0.x = (v[0].y >= 0.f) ? 1 : -1; p0.y = (v[1].y >= 0.f) ? 1 : -1;
            p0.z = (v[2].y >= 0.f) ? 1 : -1; p0.w = (v[3].y >= 0.f) ? 1 : -1;
            p1.x = (v[4].y >= 0.f) ? 1 : -1; p1.y = (v[5].y >= 0.f) ? 1 : -1;
            p1.z = (v[6].y >= 0.f) ? 1 : -1; p1.w = (v[7].y >= 0.f) ? 1 : -1;
            *(char4*)&Cc[row1]     = p0;
            *(char4*)&Cc[row1 + 4] = p1;
        }
    } else {
        float* Cf = (float*)Cout;
        const float s = (MODE == 1) ? QSCALE : 1.0f;
#pragma unroll
        for (int ip = 0; ip < 4; ip++) {
            float2 v[8];
#pragma unroll
            for (int j = 0; j < 8; j++) v[j] = f2_unpack(t2[ip][j]);
            size_t row0 = (size_t)(m0 + r0 + 2*ip) * N + n0 + c0;
            size_t row1 = row0 + N;
            float4 o;
            o.x = v[0].x*s; o.y = v[1].x*s; o.z = v[2].x*s; o.w = v[3].x*s;
            *(float4*)&Cf[row0] = o;
            o.x = v[4].x*s; o.y = v[5].x*s; o.z = v[6].x*s; o.w = v[7].x*s;
            *(float4*)&Cf[row0 + 4] = o;
            o.x = v[0].y*s; o.y = v[1].y*s; o.z = v[2].y*s; o.w = v[3].y*s;
            *(float4*)&Cf[row1] = o;
            o.x = v[4].y*s; o.y = v[5].y*s; o.z = v[6].y*s; o.w = v[7].y*s;
            *(float4*)&Cf[row1 + 4] = o;
        }
    }
}

// ---------------------------------------------------------------------------
// Attention scan (unchanged, validated).
// ---------------------------------------------------------------------------
struct AttSmem {
    float  qcT[128][132];
    float  scoresT[128][132];
    float  state[128][68];
    int8_t kc[128][144];
    int8_t kT[128][144];
    int8_t vc[128][80];
};

__device__ __forceinline__ void b4_to_f(unsigned w, float* f) {
    f[0] = (float)((int)(w << 24) >> 24);
    f[1] = (float)((int)(w << 16) >> 24);
    f[2] = (float)((int)(w <<  8) >> 24);
    f[3] = (float)((int) w        >> 24);
}

__global__ void __launch_bounds__(256)
att_kernel(const float* __restrict__ gq, const int8_t* __restrict__ gk,
           const int8_t* __restrict__ gv, float* __restrict__ gao,
           float* __restrict__ gstate, int write_state)
{
    extern __shared__ char sraw[];
    AttSmem& S = *(AttSmem*)sraw;

    const int pair = blockIdx.x;
    const int half = pair & 1;
    const int bh   = pair >> 1;
    const int b    = bh >> 4, h = bh & 15;
    const int tid  = threadIdx.x;

    for (int i = tid; i < 128 * 68; i += 256)
        ((float*)S.state)[i] = 0.f;

    const int ty = tid >> 4, tx = tid & 15;
    const int i0 = ty * 8, j0 = tx * 8, e0 = tx * 4;

    const size_t base_row = (size_t)b * SEQ;
    const int colq = h * DH;
    const int colv = h * DH + half * 64;

    const int lc = tid >> 1;
    const int dh = (tid & 1) * 64;

    for (int n = 0; n < 32; n++) {
        {
            const size_t row = base_row + (size_t)n * 128 + lc;
            const float* qs = gq + row * DM + colq + dh;
#pragma unroll
            for (int d4 = 0; d4 < 64; d4 += 4) {
                float4 v = *(const float4*)(qs + d4);
                S.qcT[dh + d4 + 0][lc] = v.x;
                S.qcT[dh + d4 + 1][lc] = v.y;
                S.qcT[dh + d4 + 2][lc] = v.z;
                S.qcT[dh + d4 + 3][lc] = v.w;
            }
            const int8_t* ks = gk + row * DM + colq + dh;
#pragma unroll
            for (int d16 = 0; d16 < 64; d16 += 16) {
                int4 kw = *(const int4*)(ks + d16);
                *(int4*)&S.kc[lc][dh + d16] = kw;
                const int8_t* kb = (const int8_t*)&kw;
#pragma unroll
                for (int z = 0; z < 16; z++)
                    S.kT[dh + d16 + z][lc] = kb[z];
            }
            const int8_t* vs = gv + row * DM + colv + (dh >> 1);
            *(int4*)&S.vc[lc][(dh >> 1) + 0]  = *(const int4*)(vs);
            *(int4*)&S.vc[lc][(dh >> 1) + 16] = *(const int4*)(vs + 16);
        }
        __syncthreads();

        float sc[8][8], cr[8][4];
#pragma unroll
        for (int i = 0; i < 8; i++) {
#pragma unroll
            for (int j = 0; j < 8; j++) sc[i][j] = 0.f;
#pragma unroll
            for (int e = 0; e < 4; e++) cr[i][e] = 0.f;
        }
        for (int kk = 0; kk < 128; kk++) {
            float4 q0 = *(const float4*)&S.qcT[kk][i0];
            float4 q1 = *(const float4*)&S.qcT[kk][i0 + 4];
            float qv[8] = {q0.x, q0.y, q0.z, q0.w, q1.x, q1.y, q1.z, q1.w};
            uint2 kw = *(const uint2*)&S.kT[kk][j0];
            float kf[8];
            b4_to_f(kw.x, kf); b4_to_f(kw.y, kf + 4);
            float4 st = *(const float4*)&S.state[kk][e0];
            float sf[4] = {st.x, st.y, st.z, st.w};
#pragma unroll
            for (int i = 0; i < 8; i++) {
#pragma unroll
                for (int j = 0; j < 8; j++)
                    sc[i][j] = fmaf(qv[i], kf[j], sc[i][j]);
#pragma unroll
                for (int e = 0; e < 4; e++)
                    cr[i][e] = fmaf(qv[i], sf[e], cr[i][e]);
            }
        }
#pragma unroll
        for (int jj = 0; jj < 8; jj++)
#pragma unroll
            for (int ii = 0; ii < 8; ii++) {
                int gi = i0 + ii, gj = j0 + jj;
                S.scoresT[gj][gi] = (gj <= gi) ? sc[ii][jj] : 0.f;
            }
        __syncthreads();

        float in8[8][4], up[8][4];
#pragma unroll
        for (int i = 0; i < 8; i++)
#pragma unroll
            for (int e = 0; e < 4; e++) { in8[i][e] = 0.f; up[i][e] = 0.f; }

        for (int kk = 0; kk < 128; kk++) {
            float4 s0 = *(const float4*)&S.scoresT[kk][i0];
            float4 s1 = *(const float4*)&S.scoresT[kk][i0 + 4];
            float sv[8] = {s0.x, s0.y, s0.z, s0.w, s1.x, s1.y, s1.z, s1.w};
            uint2 kw = *(const uint2*)&S.kc[kk][i0];
            float kf[8];
            b4_to_f(kw.x, kf); b4_to_f(kw.y, kf + 4);
            unsigned vw = *(const unsigned*)&S.vc[kk][e0];
            float vf[4];
            b4_to_f(vw, vf);
#pragma unroll
            for (int i = 0; i < 8; i++)
#pragma unroll
                for (int e = 0; e < 4; e++) {
                    in8[i][e] = fmaf(sv[i], vf[e], in8[i][e]);
                    up[i][e]  = fmaf(kf[i], vf[e], up[i][e]);
                }
        }
#pragma unroll
        for (int ii = 0; ii < 8; ii++) {
            size_t row = (base_row + (size_t)n * 128 + i0 + ii) * DM + colv + e0;
            float4 o = {cr[ii][0] + in8[ii][0], cr[ii][1] + in8[ii][1],
                        cr[ii][2] + in8[ii][2], cr[ii][3] + in8[ii][3]};
            *(float4*)&gao[row] = o;
#pragma unroll
            for (int e = 0; e < 4; e++)
                S.state[i0 + ii][e0 + e] += up[ii][e];
        }
        __syncthreads();
    }

    if (write_state) {
        for (int idx = tid; idx < 128 * 64; idx += 256) {
            int d = idx >> 6, e = idx & 63;
            gstate[(((size_t)(b * NH + h) * DH) + d) * DH + half * 64 + e]
                = S.state[d][e];
        }
    }
}

// ---------------------------------------------------------------------------
extern "C" void kernel_launch(void* const* d_in, const int* in_sizes, int n_in,
                              void* d_out, int out_size)
{
    const float* x  = (const float*)d_in[0];
    const float* Wq = (const float*)d_in[1];
    const float* Wk = (const float*)d_in[2];
    const float* Wv = (const float*)d_in[3];
    const float* Wo = (const float*)d_in[4];
    float* out = (float*)d_out;

    void *pq, *pk, *pv, *pa;
    void *px1, *px2, *pa1, *pa2, *pwq1, *pwq2, *pwo1, *pwo2;
    cudaGetSymbolAddress(&pq,  g_q);
    cudaGetSymbolAddress(&pk,  g_k);
    cudaGetSymbolAddress(&pv,  g_v);
    cudaGetSymbolAddress(&pa,  g_ao);
    cudaGetSymbolAddress(&px1, g_x1);
    cudaGetSymbolAddress(&px2, g_x2);
    cudaGetSymbolAddress(&pa1, g_a1);
    cudaGetSymbolAddress(&pa2, g_a2);
    cudaGetSymbolAddress(&pwq1, g_wq1);
    cudaGetSymbolAddress(&pwq2, g_wq2);
    cudaGetSymbolAddress(&pwo1, g_wo1);
    cudaGetSymbolAddress(&pwo2, g_wo2);

    cudaFuncSetAttribute(mmah_gemm<0>, cudaFuncAttributeMaxDynamicSharedMemorySize, MMA_SMEM);
    cudaFuncSetAttribute(mmah_gemm<1>, cudaFuncAttributeMaxDynamicSharedMemorySize, MMA_SMEM);
    cudaFuncSetAttribute(att_kernel, cudaFuncAttributeMaxDynamicSharedMemorySize,
                         (int)sizeof(AttSmem));

    // splits
    split_bf16<<<8192, 256>>>(x, (size_t)MROWS * DM,
                              (__nv_bfloat16*)px1, (__nv_bfloat16*)px2);
    split_bf16<<<1024, 256>>>(Wq, (size_t)DM * DM,
                              (__nv_bfloat16*)pwq1, (__nv_bfloat16*)pwq2);
    split_bf16<<<1024, 256>>>(Wo, (size_t)DM * DM,
                              (__nv_bfloat16*)pwo1, (__nv_bfloat16*)pwo2);

    dim3 grid(DM / 128, MROWS / 128), blk(256);
    // Q projection on tensor cores (scaled)
    mmah_gemm<1><<<grid, blk, MMA_SMEM>>>(
        (const __nv_bfloat16*)px1, (const __nv_bfloat16*)px2,
        (const __nv_bfloat16*)pwq1, (const __nv_bfloat16*)pwq2, (float*)pq);
    // K/V sign projections: exact fp32 path (bit-identical to R5)
    gemm_nt<2><<<grid, blk>>>(x, Wk, pk);
    gemm_nt<2><<<grid, blk>>>(x, Wv, pv);

    int write_state = ((size_t)out_size >= OUT_ELEMS + STATE_ELEMS) ? 1 : 0;
    att_kernel<<<128, 256, sizeof(AttSmem)>>>(
        (const float*)pq, (const int8_t*)pk, (const int8_t*)pv,
        (float*)pa, out + OUT_ELEMS, write_state);

    // Wo on tensor cores
    split_bf16<<<8192, 256>>>((const float*)pa, (size_t)MROWS * DM,
                              (__nv_bfloat16*)pa1, (__nv_bfloat16*)pa2);
    mmah_gemm<0><<<grid, blk, MMA_SMEM>>>(
        (const __nv_bfloat16*)pa1, (const __nv_bfloat16*)pa2,
        (const __nv_bfloat16*)pwo1, (const __nv_bfloat16*)pwo2, out);
}

// round 10
// speedup vs baseline: 1.4551x; 1.0276x over previous
#include <cuda_runtime.h>
#include <cuda_bf16.h>
#include <cstdint>
#include <cstddef>

#define BSZ 4
#define SEQ 4096
#define DM  2048
#define NH  16
#define DH  128
#define MROWS (BSZ*SEQ)               // 16384
#define OUT_ELEMS ((size_t)MROWS*DM)  // 33554432
#define STATE_ELEMS ((size_t)BSZ*NH*DH*DH)
#define QSCALE 0.08838834764831845f   // 1/sqrt(128)

typedef unsigned long long u64;

// ---------------- scratch (device globals: allocation-free rule) ------------
__device__ float  g_q [(size_t)MROWS*DM];
__device__ int8_t g_k [(size_t)MROWS*DM];
__device__ int8_t g_v [(size_t)MROWS*DM];
__device__ __nv_bfloat16 g_x1[(size_t)MROWS*DM];
__device__ __nv_bfloat16 g_x2[(size_t)MROWS*DM];
__device__ __nv_bfloat16 g_a1[(size_t)MROWS*DM];
__device__ __nv_bfloat16 g_a2[(size_t)MROWS*DM];
__device__ __nv_bfloat16 g_wq1[(size_t)DM*DM];
__device__ __nv_bfloat16 g_wq2[(size_t)DM*DM];
__device__ __nv_bfloat16 g_wo1[(size_t)DM*DM];
__device__ __nv_bfloat16 g_wo2[(size_t)DM*DM];

// ---------------- packed f32x2 helpers (per-lane IEEE fp32, rn) -------------
__device__ __forceinline__ u64 f2_dup(float x) {
    u64 r; asm("mov.b64 %0, {%1, %1};" : "=l"(r) : "f"(x)); return r;
}
__device__ __forceinline__ u64 f2_fma(u64 a, u64 b, u64 c) {
    u64 d; asm("fma.rn.f32x2 %0, %1, %2, %3;" : "=l"(d) : "l"(a), "l"(b), "l"(c));
    return d;
}
__device__ __forceinline__ u64 f2_add(u64 a, u64 b) {
    u64 d; asm("add.rn.f32x2 %0, %1, %2;" : "=l"(d) : "l"(a), "l"(b)); return d;
}
__device__ __forceinline__ float2 f2_unpack(u64 p) {
    float2 f; asm("mov.b64 {%0, %1}, %2;" : "=f"(f.x), "=f"(f.y) : "l"(p)); return f;
}

// ---------------- mma.sync / ldmatrix / cp.async helpers (arch-neutral) -----
__device__ __forceinline__ uint32_t smem_u32(const void* p) {
    uint32_t a;
    asm("{ .reg .u64 t; cvta.to.shared.u64 t, %1; cvt.u32.u64 %0, t; }"
        : "=r"(a) : "l"(p));
    return a;
}
__device__ __forceinline__ void ldsm4(uint32_t* r, uint32_t addr) {
    asm volatile("ldmatrix.sync.aligned.m8n8.x4.shared.b16 {%0,%1,%2,%3}, [%4];"
        : "=r"(r[0]), "=r"(r[1]), "=r"(r[2]), "=r"(r[3]) : "r"(addr));
}
__device__ __forceinline__ void mma_bf16(float* c, const uint32_t* a,
                                         const uint32_t* b) {
    asm volatile(
        "mma.sync.aligned.m16n8k16.row.col.f32.bf16.bf16.f32 "
        "{%0,%1,%2,%3}, {%4,%5,%6,%7}, {%8,%9}, {%0,%1,%2,%3};"
        : "+f"(c[0]), "+f"(c[1]), "+f"(c[2]), "+f"(c[3])
        : "r"(a[0]), "r"(a[1]), "r"(a[2]), "r"(a[3]), "r"(b[0]), "r"(b[1]));
}
#define CPA(dst, src) asm volatile("cp.async.cg.shared.global [%0], [%1], 16;" :: "r"(dst), "l"(src))
#define CPC()         asm volatile("cp.async.commit_group;")
#define CPW0()        asm volatile("cp.async.wait_group 0;")
#define CPW2()        asm volatile("cp.async.wait_group 2;")

// ---------------------------------------------------------------------------
// split: fp32 -> bf16 hi + bf16 lo
// ---------------------------------------------------------------------------
__global__ void split_bf16(const float* __restrict__ s, size_t n,
                           __nv_bfloat16* __restrict__ hi,
                           __nv_bfloat16* __restrict__ lo)
{
    size_t stride = (size_t)gridDim.x * blockDim.x * 4;
    for (size_t i = ((size_t)blockIdx.x * blockDim.x + threadIdx.x) * 4;
         i < n; i += stride) {
        float4 v = *(const float4*)(s + i);
        __nv_bfloat16 hx = __float2bfloat16(v.x);
        __nv_bfloat16 hy = __float2bfloat16(v.y);
        __nv_bfloat16 hz = __float2bfloat16(v.z);
        __nv_bfloat16 hw = __float2bfloat16(v.w);
        __nv_bfloat16 lx = __float2bfloat16(v.x - __bfloat162float(hx));
        __nv_bfloat16 ly = __float2bfloat16(v.y - __bfloat162float(hy));
        __nv_bfloat16 lz = __float2bfloat16(v.z - __bfloat162float(hz));
        __nv_bfloat16 lw = __float2bfloat16(v.w - __bfloat162float(hw));
        *(__nv_bfloat162*)(hi + i)     = __nv_bfloat162(hx, hy);
        *(__nv_bfloat162*)(hi + i + 2) = __nv_bfloat162(hz, hw);
        *(__nv_bfloat162*)(lo + i)     = __nv_bfloat162(lx, ly);
        *(__nv_bfloat162*)(lo + i + 2) = __nv_bfloat162(lz, lw);
    }
}

// ---------------------------------------------------------------------------
// 2-split bf16 mma GEMM (NT), 2-stage pipeline. MODE 1: out * QSCALE.
// (Validated in R7/R8 — unchanged.)
// ---------------------------------------------------------------------------
#define RS   40
#define TILE_B (128 * RS * 2)          // 10240
#define BUF_B  (4 * TILE_B)            // 40960
#define MMA_SMEM  (2 * BUF_B)          // 81920
#define MMA4_SMEM (4 * BUF_B)          // 163840

template<int MODE>
__global__ void __launch_bounds__(256, 1)
mmah_gemm(const __nv_bfloat16* __restrict__ A1, const __nv_bfloat16* __restrict__ A2,
          const __nv_bfloat16* __restrict__ B1, const __nv_bfloat16* __restrict__ B2,
          float* __restrict__ C)
{
    extern __shared__ char sm[];
    const uint32_t smb = smem_u32(sm);
    const int tid = threadIdx.x, lane = tid & 31, w = tid >> 5;
    const int m0 = blockIdx.y * 128, n0 = blockIdx.x * 128;
    const int wm = (w & 3) * 32, wn = (w >> 2) * 64;

    const __nv_bfloat16* src[4] = {A1, A2, B1, B2};
    const int rbs[4] = {m0, m0, n0, n0};
    constexpr int NT = DM / 32;   // 64 stages

    auto issue = [&](int t) {
        const uint32_t bb = smb + (uint32_t)(t & 1) * BUF_B;
        const int k0 = t * 32;
#pragma unroll
        for (int i = 0; i < 2; i++) {
            const int c = tid + 256 * i;
            const int row = c >> 2, col8 = (c & 3) * 8;
#pragma unroll
            for (int X = 0; X < 4; X++) {
                uint32_t dst = bb + (uint32_t)X * TILE_B + row * (RS * 2) + col8 * 2;
                const __nv_bfloat16* s = src[X] + (size_t)(rbs[X] + row) * DM + k0 + col8;
                CPA(dst, s);
            }
        }
    };

    float acc[2][8][4];
#pragma unroll
    for (int mt = 0; mt < 2; mt++)
#pragma unroll
        for (int nt = 0; nt < 8; nt++)
#pragma unroll
            for (int e = 0; e < 4; e++) acc[mt][nt][e] = 0.f;

    issue(0); CPC();

    const int arow = wm + (lane & 15);
    const uint32_t acolo = ((lane >> 4) << 3) * 2;
    const int brow = wn + (lane & 7) + ((lane >> 4) << 3);
    const uint32_t bcolo = (((lane >> 3) & 1) << 3) * 2;

    for (int t = 0; t < NT; t++) {
        CPW0();
        __syncthreads();
        if (t + 1 < NT) { issue(t + 1); CPC(); }

        const uint32_t bb = smb + (uint32_t)(t & 1) * BUF_B;
#pragma unroll
        for (int ks = 0; ks < 32; ks += 16) {
            const uint32_t ko = (uint32_t)ks * 2;
            uint32_t a1f[2][4], a2f[2][4], b1f[8][2], b2f[8][2];
            ldsm4(a1f[0], bb + 0*TILE_B + (arow     ) * (RS*2) + ko + acolo);
            ldsm4(a1f[1], bb + 0*TILE_B + (arow + 16) * (RS*2) + ko + acolo);
            ldsm4(a2f[0], bb + 1*TILE_B + (arow     ) * (RS*2) + ko + acolo);
            ldsm4(a2f[1], bb + 1*TILE_B + (arow + 16) * (RS*2) + ko + acolo);
#pragma unroll
            for (int np = 0; np < 4; np++) {
                uint32_t r[4];
                ldsm4(r, bb + 2*TILE_B + (brow + np*16) * (RS*2) + ko + bcolo);
                b1f[np*2][0] = r[0]; b1f[np*2][1] = r[1];
                b1f[np*2+1][0] = r[2]; b1f[np*2+1][1] = r[3];
                ldsm4(r, bb + 3*TILE_B + (brow + np*16) * (RS*2) + ko + bcolo);
                b2f[np*2][0] = r[0]; b2f[np*2][1] = r[1];
                b2f[np*2+1][0] = r[2]; b2f[np*2+1][1] = r[3];
            }
#pragma unroll
            for (int mt = 0; mt < 2; mt++)
#pragma unroll
                for (int nt = 0; nt < 8; nt++) {
                    mma_bf16(acc[mt][nt], a1f[mt], b1f[nt]);
                    mma_bf16(acc[mt][nt], a1f[mt], b2f[nt]);
                    mma_bf16(acc[mt][nt], a2f[mt], b1f[nt]);
                }
        }
        __syncthreads();
    }

    const float s = (MODE == 1) ? QSCALE : 1.0f;
#pragma unroll
    for (int mt = 0; mt < 2; mt++)
#pragma unroll
        for (int nt = 0; nt < 8; nt++) {
            const int m = m0 + wm + mt * 16 + (lane >> 2);
            const int n = n0 + wn + nt * 8 + 2 * (lane & 3);
            float2 o0 = {acc[mt][nt][0] * s, acc[mt][nt][1] * s};
            float2 o1 = {acc[mt][nt][2] * s, acc[mt][nt][3] * s};
            *(float2*)&C[(size_t)m * DM + n]       = o0;
            *(float2*)&C[(size_t)(m + 8) * DM + n] = o1;
        }
}

// ---------------------------------------------------------------------------
// Same GEMM, 4-stage cp.async ring (deeper latency hiding) — used for Wo.
// Accumulation order identical to the 2-stage version -> bit-identical.
// ---------------------------------------------------------------------------
__global__ void __launch_bounds__(256, 1)
mmah_gemm4(const __nv_bfloat16* __restrict__ A1, const __nv_bfloat16* __restrict__ A2,
           const __nv_bfloat16* __restrict__ B1, const __nv_bfloat16* __restrict__ B2,
           float* __restrict__ C)
{
    extern __shared__ char sm[];
    const uint32_t smb = smem_u32(sm);
    const int tid = threadIdx.x, lane = tid & 31, w = tid >> 5;
    const int m0 = blockIdx.y * 128, n0 = blockIdx.x * 128;
    const int wm = (w & 3) * 32, wn = (w >> 2) * 64;

    const __nv_bfloat16* src[4] = {A1, A2, B1, B2};
    const int rbs[4] = {m0, m0, n0, n0};
    constexpr int NT = DM / 32;   // 64 stages

    auto issue = [&](int t) {
        const uint32_t bb = smb + (uint32_t)(t & 3) * BUF_B;
        const int k0 = t * 32;
#pragma unroll
        for (int i = 0; i < 2; i++) {
            const int c = tid + 256 * i;
            const int row = c >> 2, col8 = (c & 3) * 8;
#pragma unroll
            for (int X = 0; X < 4; X++) {
                uint32_t dst = bb + (uint32_t)X * TILE_B + row * (RS * 2) + col8 * 2;
                const __nv_bfloat16* s = src[X] + (size_t)(rbs[X] + row) * DM + k0 + col8;
                CPA(dst, s);
            }
        }
    };

    float acc[2][8][4];
#pragma unroll
    for (int mt = 0; mt < 2; mt++)
#pragma unroll
        for (int nt = 0; nt < 8; nt++)
#pragma unroll
            for (int e = 0; e < 4; e++) acc[mt][nt][e] = 0.f;

    issue(0); CPC(); issue(1); CPC(); issue(2); CPC();

    const int arow = wm + (lane & 15);
    const uint32_t acolo = ((lane >> 4) << 3) * 2;
    const int brow = wn + (lane & 7) + ((lane >> 4) << 3);
    const uint32_t bcolo = (((lane >> 3) & 1) << 3) * 2;

    for (int t = 0; t < NT; t++) {
        CPW2();                 // stage t's group complete (<=2 younger pending)
        __syncthreads();        // all warps past compute(t-1); buffers safe
        if (t + 3 < NT) { issue(t + 3); CPC(); }

        const uint32_t bb = smb + (uint32_t)(t & 3) * BUF_B;
#pragma unroll
        for (int ks = 0; ks < 32; ks += 16) {
            const uint32_t ko = (uint32_t)ks * 2;
            uint32_t a1f[2][4], a2f[2][4], b1f[8][2], b2f[8][2];
            ldsm4(a1f[0], bb + 0*TILE_B + (arow     ) * (RS*2) + ko + acolo);
            ldsm4(a1f[1], bb + 0*TILE_B + (arow + 16) * (RS*2) + ko + acolo);
            ldsm4(a2f[0], bb + 1*TILE_B + (arow     ) * (RS*2) + ko + acolo);
            ldsm4(a2f[1], bb + 1*TILE_B + (arow + 16) * (RS*2) + ko + acolo);
#pragma unroll
            for (int np = 0; np < 4; np++) {
                uint32_t r[4];
                ldsm4(r, bb + 2*TILE_B + (brow + np*16) * (RS*2) + ko + bcolo);
                b1f[np*2][0] = r[0]; b1f[np*2][1] = r[1];
                b1f[np*2+1][0] = r[2]; b1f[np*2+1][1] = r[3];
                ldsm4(r, bb + 3*TILE_B + (brow + np*16) * (RS*2) + ko + bcolo);
                b2f[np*2][0] = r[0]; b2f[np*2][1] = r[1];
                b2f[np*2+1][0] = r[2]; b2f[np*2+1][1] = r[3];
            }
#pragma unroll
            for (int mt = 0; mt < 2; mt++)
#pragma unroll
                for (int nt = 0; nt < 8; nt++) {
                    mma_bf16(acc[mt][nt], a1f[mt], b1f[nt]);
                    mma_bf16(acc[mt][nt], a1f[mt], b2f[nt]);
                    mma_bf16(acc[mt][nt], a2f[mt], b1f[nt]);
                }
        }
    }

#pragma unroll
    for (int mt = 0; mt < 2; mt++)
#pragma unroll
        for (int nt = 0; nt < 8; nt++) {
            const int m = m0 + wm + mt * 16 + (lane >> 2);
            const int n = n0 + wn + nt * 8 + 2 * (lane & 3);
            float2 o0 = {acc[mt][nt][0], acc[mt][nt][1]};
            float2 o1 = {acc[mt][nt][2], acc[mt][nt][3]};
            *(float2*)&C[(size_t)m * DM + n]       = o0;
            *(float2*)&C[(size_t)(m + 8) * DM + n] = o1;
        }
}

// ---------------------------------------------------------------------------
// fp32 FFMA2 GEMM (NT) — K/V sign projections (MODE 2). Bit-identical to the
// R5/R7-validated path. DO NOT TOUCH (rel_err depends on exact rounding).
// ---------------------------------------------------------------------------
template<int MODE>
__global__ void __launch_bounds__(256)
gemm_nt(const float* __restrict__ A, const float* __restrict__ B,
        void* __restrict__ Cout)
{
    constexpr int K = DM, N = DM, BK = 16, NT = K / BK;
    __shared__ float As[2][BK][132];
    __shared__ float Bs[2][BK][132];

    const int tid = threadIdx.x;
    const int m0 = blockIdx.y * 128, n0 = blockIdx.x * 128;
    const int lr = tid >> 2;
    const int lk = (tid & 3) << 2;

    const float* Ag  = A + (size_t)(m0 + lr) * K + lk;
    const float* Ag2 = Ag + (size_t)64 * K;
    const float* Bg  = B + (size_t)(n0 + lr) * K + lk;
    const float* Bg2 = Bg + (size_t)64 * K;

    {
        float4 a0 = *(const float4*)(Ag);
        float4 a1 = *(const float4*)(Ag2);
        float4 b0 = *(const float4*)(Bg);
        float4 b1 = *(const float4*)(Bg2);
        As[0][lk+0][lr]    = a0.x; As[0][lk+1][lr]    = a0.y;
        As[0][lk+2][lr]    = a0.z; As[0][lk+3][lr]    = a0.w;
        As[0][lk+0][lr+64] = a1.x; As[0][lk+1][lr+64] = a1.y;
        As[0][lk+2][lr+64] = a1.z; As[0][lk+3][lr+64] = a1.w;
        Bs[0][lk+0][lr]    = b0.x; Bs[0][lk+1][lr]    = b0.y;
        Bs[0][lk+2][lr]    = b0.z; Bs[0][lk+3][lr]    = b0.w;
        Bs[0][lk+0][lr+64] = b1.x; Bs[0][lk+1][lr+64] = b1.y;
        Bs[0][lk+2][lr+64] = b1.z; Bs[0][lk+3][lr+64] = b1.w;
    }
    __syncthreads();

    const int ty = tid >> 4, tx = tid & 15;
    const int r0 = ty * 8, c0 = tx * 8;

    u64 t2[4][8];
    u64 a2[4][8];
#pragma unroll
    for (int ip = 0; ip < 4; ip++)
#pragma unroll
        for (int j = 0; j < 8; j++) {
            t2[ip][j] = 0ull;
            if (MODE == 2) a2[ip][j] = 0ull;
        }

    for (int t = 0; t < NT; t++) {
        const int cur = t & 1;
        float4 na0, na1, nb0, nb1;
        const bool more = (t + 1 < NT);
        if (more) {
            const int off = (t + 1) * BK;
            na0 = *(const float4*)(Ag  + off);
            na1 = *(const float4*)(Ag2 + off);
            nb0 = *(const float4*)(Bg  + off);
            nb1 = *(const float4*)(Bg2 + off);
        }
#pragma unroll
        for (int kk = 0; kk < BK; kk++) {
            u64 ap0 = *(const u64*)&As[cur][kk][r0 + 0];
            u64 ap1 = *(const u64*)&As[cur][kk][r0 + 2];
            u64 ap2 = *(const u64*)&As[cur][kk][r0 + 4];
            u64 ap3 = *(const u64*)&As[cur][kk][r0 + 6];
            float4 y0 = *(const float4*)&Bs[cur][kk][c0];
            float4 y1 = *(const float4*)&Bs[cur][kk][c0 + 4];
            u64 bd[8];
            bd[0] = f2_dup(y0.x); bd[1] = f2_dup(y0.y);
            bd[2] = f2_dup(y0.z); bd[3] = f2_dup(y0.w);
            bd[4] = f2_dup(y1.x); bd[5] = f2_dup(y1.y);
            bd[6] = f2_dup(y1.z); bd[7] = f2_dup(y1.w);
#pragma unroll
            for (int j = 0; j < 8; j++) {
                t2[0][j] = f2_fma(ap0, bd[j], t2[0][j]);
                t2[1][j] = f2_fma(ap1, bd[j], t2[1][j]);
                t2[2][j] = f2_fma(ap2, bd[j], t2[2][j]);
                t2[3][j] = f2_fma(ap3, bd[j], t2[3][j]);
            }
        }
        if (MODE == 2) {
            if ((t & 3) == 3) {
#pragma unroll
                for (int ip = 0; ip < 4; ip++)
#pragma unroll
                    for (int j = 0; j < 8; j++) {
                        a2[ip][j] = f2_add(a2[ip][j], t2[ip][j]);
                        t2[ip][j] = 0ull;
                    }
            }
        }
        if (more) {
            const int nb = cur ^ 1;
            As[nb][lk+0][lr]    = na0.x; As[nb][lk+1][lr]    = na0.y;
            As[nb][lk+2][lr]    = na0.z; As[nb][lk+3][lr]    = na0.w;
            As[nb][lk+0][lr+64] = na1.x; As[nb][lk+1][lr+64] = na1.y;
            As[nb][lk+2][lr+64] = na1.z; As[nb][lk+3][lr+64] = na1.w;
            Bs[nb][lk+0][lr]    = nb0.x; Bs[nb][lk+1][lr]    = nb0.y;
            Bs[nb][lk+2][lr]    = nb0.z; Bs[nb][lk+3][lr]    = nb0.w;
            Bs[nb][lk+0][lr+64] = nb1.x; Bs[nb][lk+1][lr+64] = nb1.y;
            Bs[nb][lk+2][lr+64] = nb1.z; Bs[nb][lk+3][lr+64] = nb1.w;
        }
        __syncthreads();
    }

    if (MODE == 2) {
        int8_t* Cc = (int8_t*)Cout;
#pragma unroll
        for (int ip = 0; ip < 4; ip++) {
            float2 v[8];
#pragma unroll
            for (int j = 0; j < 8; j++) v[j] = f2_unpack(a2[ip][j]);
            size_t row0 = (size_t)(m0 + r0 + 2*ip) * N + n0 + c0;
            size_t row1 = row0 + N;
            char4 p0, p1;
            p0.x = (v[0].x >= 0.f) ? 1 : -1; p0.y = (v[1].x >= 0.f) ? 1 : -1;
            p0.z = (v[2].x >= 0.f) ? 1 : -1; p0.w = (v[3].x >= 0.f) ? 1 : -1;
            p1.x = (v[4].x >= 0.f) ? 1 : -1; p1.y = (v[5].x >= 0.f) ? 1 : -1;
            p1.z = (v[6].x >= 0.f) ? 1 : -1; p1.w = (v[7].x >= 0.f) ? 1 : -1;
            *(char4*)&Cc[row0]     = p0;
            *(char4*)&Cc[row0 + 4] = p1;
            p0.x = (v[0].y >= 0.f) ? 1 : -1; p0.y = (v[1].y >= 0.f) ? 1 : -1;
            p0.z = (v[2].y >= 0.f) ? 1 : -1; p0.w = (v[3].y >= 0.f) ? 1 : -1;
            p1.x = (v[4].y >= 0.f) ? 1 : -1; p1.y = (v[5].y >= 0.f) ? 1 : -1;
            p1.z = (v[6].y >= 0.f) ? 1 : -1; p1.w = (v[7].y >= 0.f) ? 1 : -1;
            *(char4*)&Cc[row1]     = p0;
            *(char4*)&Cc[row1 + 4] = p1;
        }
    } else {
        float* Cf = (float*)Cout;
        const float s = (MODE == 1) ? QSCALE : 1.0f;
#pragma unroll
        for (int ip = 0; ip < 4; ip++) {
            float2 v[8];
#pragma unroll
            for (int j = 0; j < 8; j++) v[j] = f2_unpack(t2[ip][j]);
            size_t row0 = (size_t)(m0 + r0 + 2*ip) * N + n0 + c0;
            size_t row1 = row0 + N;
            float4 o;
            o.x = v[0].x*s; o.y = v[1].x*s; o.z = v[2].x*s; o.w = v[3].x*s;
            *(float4*)&Cf[row0] = o;
            o.x = v[4].x*s; o.y = v[5].x*s; o.z = v[6].x*s; o.w = v[7].x*s;
            *(float4*)&Cf[row0 + 4] = o;
            o.x = v[0].y*s; o.y = v[1].y*s; o.z = v[2].y*s; o.w = v[3].y*s;
            *(float4*)&Cf[row1] = o;
            o.x = v[4].y*s; o.y = v[5].y*s; o.z = v[6].y*s; o.w = v[7].y*s;
            *(float4*)&Cf[row1 + 4] = o;
        }
    }
}

// ---------------------------------------------------------------------------
// Attention scan. Epilogue now writes the bf16 2-split of the output
// directly (same arithmetic as split_bf16 on the same fp32 values).
// ---------------------------------------------------------------------------
struct AttSmem {
    float  qcT[128][132];
    float  scoresT[128][132];
    float  state[128][68];
    int8_t kc[128][144];
    int8_t kT[128][144];
    int8_t vc[128][80];
};

__device__ __forceinline__ void b4_to_f(unsigned w, float* f) {
    f[0] = (float)((int)(w << 24) >> 24);
    f[1] = (float)((int)(w << 16) >> 24);
    f[2] = (float)((int)(w <<  8) >> 24);
    f[3] = (float)((int) w        >> 24);
}

__global__ void __launch_bounds__(256)
att_kernel(const float* __restrict__ gq, const int8_t* __restrict__ gk,
           const int8_t* __restrict__ gv,
           __nv_bfloat16* __restrict__ ga1, __nv_bfloat16* __restrict__ ga2,
           float* __restrict__ gstate, int write_state)
{
    extern __shared__ char sraw[];
    AttSmem& S = *(AttSmem*)sraw;

    const int pair = blockIdx.x;
    const int half = pair & 1;
    const int bh   = pair >> 1;
    const int b    = bh >> 4, h = bh & 15;
    const int tid  = threadIdx.x;

    for (int i = tid; i < 128 * 68; i += 256)
        ((float*)S.state)[i] = 0.f;

    const int ty = tid >> 4, tx = tid & 15;
    const int i0 = ty * 8, j0 = tx * 8, e0 = tx * 4;

    const size_t base_row = (size_t)b * SEQ;
    const int colq = h * DH;
    const int colv = h * DH + half * 64;

    const int lc = tid >> 1;
    const int dh = (tid & 1) * 64;

    for (int n = 0; n < 32; n++) {
        {
            const size_t row = base_row + (size_t)n * 128 + lc;
            const float* qs = gq + row * DM + colq + dh;
#pragma unroll
            for (int d4 = 0; d4 < 64; d4 += 4) {
                float4 v = *(const float4*)(qs + d4);
                S.qcT[dh + d4 + 0][lc] = v.x;
                S.qcT[dh + d4 + 1][lc] = v.y;
                S.qcT[dh + d4 + 2][lc] = v.z;
                S.qcT[dh + d4 + 3][lc] = v.w;
            }
            const int8_t* ks = gk + row * DM + colq + dh;
#pragma unroll
            for (int d16 = 0; d16 < 64; d16 += 16) {
                int4 kw = *(const int4*)(ks + d16);
                *(int4*)&S.kc[lc][dh + d16] = kw;
                const int8_t* kb = (const int8_t*)&kw;
#pragma unroll
                for (int z = 0; z < 16; z++)
                    S.kT[dh + d16 + z][lc] = kb[z];
            }
            const int8_t* vs = gv + row * DM + colv + (dh >> 1);
            *(int4*)&S.vc[lc][(dh >> 1) + 0]  = *(const int4*)(vs);
            *(int4*)&S.vc[lc][(dh >> 1) + 16] = *(const int4*)(vs + 16);
        }
        __syncthreads();

        float sc[8][8], cr[8][4];
#pragma unroll
        for (int i = 0; i < 8; i++) {
#pragma unroll
            for (int j = 0; j < 8; j++) sc[i][j] = 0.f;
#pragma unroll
            for (int e = 0; e < 4; e++) cr[i][e] = 0.f;
        }
        for (int kk = 0; kk < 128; kk++) {
            float4 q0 = *(const float4*)&S.qcT[kk][i0];
            float4 q1 = *(const float4*)&S.qcT[kk][i0 + 4];
            float qv[8] = {q0.x, q0.y, q0.z, q0.w, q1.x, q1.y, q1.z, q1.w};
            uint2 kw = *(const uint2*)&S.kT[kk][j0];
            float kf[8];
            b4_to_f(kw.x, kf); b4_to_f(kw.y, kf + 4);
            float4 st = *(const float4*)&S.state[kk][e0];
            float sf[4] = {st.x, st.y, st.z, st.w};
#pragma unroll
            for (int i = 0; i < 8; i++) {
#pragma unroll
                for (int j = 0; j < 8; j++)
                    sc[i][j] = fmaf(qv[i], kf[j], sc[i][j]);
#pragma unroll
                for (int e = 0; e < 4; e++)
                    cr[i][e] = fmaf(qv[i], sf[e], cr[i][e]);
            }
        }
#pragma unroll
        for (int jj = 0; jj < 8; jj++)
#pragma unroll
            for (int ii = 0; ii < 8; ii++) {
                int gi = i0 + ii, gj = j0 + jj;
                S.scoresT[gj][gi] = (gj <= gi) ? sc[ii][jj] : 0.f;
            }
        __syncthreads();

        float in8[8][4], up[8][4];
#pragma unroll
        for (int i = 0; i < 8; i++)
#pragma unroll
            for (int e = 0; e < 4; e++) { in8[i][e] = 0.f; up[i][e] = 0.f; }

        for (int kk = 0; kk < 128; kk++) {
            float4 s0 = *(const float4*)&S.scoresT[kk][i0];
            float4 s1 = *(const float4*)&S.scoresT[kk][i0 + 4];
            float sv[8] = {s0.x, s0.y, s0.z, s0.w, s1.x, s1.y, s1.z, s1.w};
            uint2 kw = *(const uint2*)&S.kc[kk][i0];
            float kf[8];
            b4_to_f(kw.x, kf); b4_to_f(kw.y, kf + 4);
            unsigned vw = *(const unsigned*)&S.vc[kk][e0];
            float vf[4];
            b4_to_f(vw, vf);
#pragma unroll
            for (int i = 0; i < 8; i++)
#pragma unroll
                for (int e = 0; e < 4; e++) {
                    in8[i][e] = fmaf(sv[i], vf[e], in8[i][e]);
                    up[i][e]  = fmaf(kf[i], vf[e], up[i][e]);
                }
        }
#pragma unroll
        for (int ii = 0; ii < 8; ii++) {
            size_t row = (base_row + (size_t)n * 128 + i0 + ii) * DM + colv + e0;
            float o[4] = {cr[ii][0] + in8[ii][0], cr[ii][1] + in8[ii][1],
                          cr[ii][2] + in8[ii][2], cr[ii][3] + in8[ii][3]};
            __nv_bfloat16 hb[4], lb[4];
#pragma unroll
            for (int e = 0; e < 4; e++) {
                hb[e] = __float2bfloat16(o[e]);
                lb[e] = __float2bfloat16(o[e] - __bfloat162float(hb[e]));
            }
            *(__nv_bfloat162*)(ga1 + row)     = __nv_bfloat162(hb[0], hb[1]);
            *(__nv_bfloat162*)(ga1 + row + 2) = __nv_bfloat162(hb[2], hb[3]);
            *(__nv_bfloat162*)(ga2 + row)     = __nv_bfloat162(lb[0], lb[1]);
            *(__nv_bfloat162*)(ga2 + row + 2) = __nv_bfloat162(lb[2], lb[3]);
#pragma unroll
            for (int e = 0; e < 4; e++)
                S.state[i0 + ii][e0 + e] += up[ii][e];
        }
        __syncthreads();
    }

    if (write_state) {
        for (int idx = tid; idx < 128 * 64; idx += 256) {
            int d = idx >> 6, e = idx & 63;
            gstate[(((size_t)(b * NH + h) * DH) + d) * DH + half * 64 + e]
                = S.state[d][e];
        }
    }
}

// ---------------------------------------------------------------------------
extern "C" void kernel_launch(void* const* d_in, const int* in_sizes, int n_in,
                              void* d_out, int out_size)
{
    const float* x  = (const float*)d_in[0];
    const float* Wq = (const float*)d_in[1];
    const float* Wk = (const float*)d_in[2];
    const float* Wv = (const float*)d_in[3];
    const float* Wo = (const float*)d_in[4];
    float* out = (float*)d_out;

    void *pq, *pk, *pv;
    void *px1, *px2, *pa1, *pa2, *pwq1, *pwq2, *pwo1, *pwo2;
    cudaGetSymbolAddress(&pq,  g_q);
    cudaGetSymbolAddress(&pk,  g_k);
    cudaGetSymbolAddress(&pv,  g_v);
    cudaGetSymbolAddress(&px1, g_x1);
    cudaGetSymbolAddress(&px2, g_x2);
    cudaGetSymbolAddress(&pa1, g_a1);
    cudaGetSymbolAddress(&pa2, g_a2);
    cudaGetSymbolAddress(&pwq1, g_wq1);
    cudaGetSymbolAddress(&pwq2, g_wq2);
    cudaGetSymbolAddress(&pwo1, g_wo1);
    cudaGetSymbolAddress(&pwo2, g_wo2);

    cudaFuncSetAttribute(mmah_gemm<1>, cudaFuncAttributeMaxDynamicSharedMemorySize, MMA_SMEM);
    cudaFuncSetAttribute(mmah_gemm4,  cudaFuncAttributeMaxDynamicSharedMemorySize, MMA4_SMEM);
    cudaFuncSetAttribute(att_kernel, cudaFuncAttributeMaxDynamicSharedMemorySize,
                         (int)sizeof(AttSmem));

    // fork-join streams for K/V overlap (created per call; host-side objects)
    cudaStream_t s1, s2;
    cudaEvent_t e0, eK, eV;
    cudaStreamCreateWithFlags(&s1, cudaStreamNonBlocking);
    cudaStreamCreateWithFlags(&s2, cudaStreamNonBlocking);
    cudaEventCreateWithFlags(&e0, cudaEventDisableTiming);
    cudaEventCreateWithFlags(&eK, cudaEventDisableTiming);
    cudaEventCreateWithFlags(&eV, cudaEventDisableTiming);

    dim3 grid(DM / 128, MROWS / 128), blk(256);

    // fork
    cudaEventRecord(e0, 0);
    cudaStreamWaitEvent(s1, e0, 0);
    cudaStreamWaitEvent(s2, e0, 0);

    // side streams: K / V fp32 sign projections (fma-pipe bound)
    gemm_nt<2><<<grid, blk, 0, s1>>>(x, Wk, pk);
    cudaEventRecord(eK, s1);
    gemm_nt<2><<<grid, blk, 0, s2>>>(x, Wv, pv);
    cudaEventRecord(eV, s2);

    // main stream: splits + Q projection (tensor/mem bound) overlap with K/V
    split_bf16<<<8192, 256>>>(x, (size_t)MROWS * DM,
                              (__nv_bfloat16*)px1, (__nv_bfloat16*)px2);
    split_bf16<<<1024, 256>>>(Wq, (size_t)DM * DM,
                              (__nv_bfloat16*)pwq1, (__nv_bfloat16*)pwq2);
    split_bf16<<<1024, 256>>>(Wo, (size_t)DM * DM,
                              (__nv_bfloat16*)pwo1, (__nv_bfloat16*)pwo2);
    mmah_gemm<1><<<grid, blk, MMA_SMEM>>>(
        (const __nv_bfloat16*)px1, (const __nv_bfloat16*)px2,
        (const __nv_bfloat16*)pwq1, (const __nv_bfloat16*)pwq2, (float*)pq);

    // join
    cudaStreamWaitEvent(0, eK, 0);
    cudaStreamWaitEvent(0, eV, 0);

    int write_state = ((size_t)out_size >= OUT_ELEMS + STATE_ELEMS) ? 1 : 0;
    att_kernel<<<128, 256, sizeof(AttSmem)>>>(
        (const float*)pq, (const int8_t*)pk, (const int8_t*)pv,
        (__nv_bfloat16*)pa1, (__nv_bfloat16*)pa2, out + OUT_ELEMS, write_state);

    // Wo on tensor cores (4-stage pipeline)
    mmah_gemm4<<<grid, blk, MMA4_SMEM>>>(
        (const __nv_bfloat16*)pa1, (const __nv_bfloat16*)pa2,
        (const __nv_bfloat16*)pwo1, (const __nv_bfloat16*)pwo2, out);

    cudaEventDestroy(e0);
    cudaEventDestroy(eK);
    cudaEventDestroy(eV);
    cudaStreamDestroy(s1);
    cudaStreamDestroy(s2);
}

// round 11
// speedup vs baseline: 2.2407x; 1.5399x over previous
#include <cuda_runtime.h>
#include <cuda_bf16.h>
#include <cstdint>
#include <cstddef>

#define BSZ 4
#define SEQ 4096
#define DM  2048
#define NH  16
#define DH  128
#define MROWS (BSZ*SEQ)               // 16384
#define OUT_ELEMS ((size_t)MROWS*DM)  // 33554432
#define STATE_ELEMS ((size_t)BSZ*NH*DH*DH)
#define QSCALE 0.08838834764831845f   // 1/sqrt(128)
#define TAU 2.5e-4f                   // sign-ambiguity threshold (>=10x bound)
#define CAND_CAP 262144

typedef unsigned long long u64;

// ---------------- scratch (device globals: allocation-free rule) ------------
__device__ float  g_q [(size_t)MROWS*DM];
__device__ int8_t g_k [(size_t)MROWS*DM];
__device__ int8_t g_v [(size_t)MROWS*DM];
__device__ __nv_bfloat16 g_x1[(size_t)MROWS*DM];
__device__ __nv_bfloat16 g_x2[(size_t)MROWS*DM];
__device__ __nv_bfloat16 g_a1[(size_t)MROWS*DM];
__device__ __nv_bfloat16 g_a2[(size_t)MROWS*DM];
__device__ __nv_bfloat16 g_wq1[(size_t)DM*DM];
__device__ __nv_bfloat16 g_wq2[(size_t)DM*DM];
__device__ __nv_bfloat16 g_wk1[(size_t)DM*DM];
__device__ __nv_bfloat16 g_wk2[(size_t)DM*DM];
__device__ __nv_bfloat16 g_wv1[(size_t)DM*DM];
__device__ __nv_bfloat16 g_wv2[(size_t)DM*DM];
__device__ __nv_bfloat16 g_wo1[(size_t)DM*DM];
__device__ __nv_bfloat16 g_wo2[(size_t)DM*DM];
__device__ uint32_t g_cand[CAND_CAP];
__device__ uint32_t g_ncand;

// ---------------- mma.sync / ldmatrix / cp.async helpers --------------------
__device__ __forceinline__ uint32_t smem_u32(const void* p) {
    uint32_t a;
    asm("{ .reg .u64 t; cvta.to.shared.u64 t, %1; cvt.u32.u64 %0, t; }"
        : "=r"(a) : "l"(p));
    return a;
}
__device__ __forceinline__ void ldsm4(uint32_t* r, uint32_t addr) {
    asm volatile("ldmatrix.sync.aligned.m8n8.x4.shared.b16 {%0,%1,%2,%3}, [%4];"
        : "=r"(r[0]), "=r"(r[1]), "=r"(r[2]), "=r"(r[3]) : "r"(addr));
}
__device__ __forceinline__ void mma_bf16(float* c, const uint32_t* a,
                                         const uint32_t* b) {
    asm volatile(
        "mma.sync.aligned.m16n8k16.row.col.f32.bf16.bf16.f32 "
        "{%0,%1,%2,%3}, {%4,%5,%6,%7}, {%8,%9}, {%0,%1,%2,%3};"
        : "+f"(c[0]), "+f"(c[1]), "+f"(c[2]), "+f"(c[3])
        : "r"(a[0]), "r"(a[1]), "r"(a[2]), "r"(a[3]), "r"(b[0]), "r"(b[1]));
}
#define CPA(dst, src) asm volatile("cp.async.cg.shared.global [%0], [%1], 16;" :: "r"(dst), "l"(src))
#define CPC()         asm volatile("cp.async.commit_group;")
#define CPW0()        asm volatile("cp.async.wait_group 0;")
#define CPW2()        asm volatile("cp.async.wait_group 2;")

// ---------------------------------------------------------------------------
// split: fp32 -> bf16 hi + bf16 lo
// ---------------------------------------------------------------------------
__global__ void split_bf16(const float* __restrict__ s, size_t n,
                           __nv_bfloat16* __restrict__ hi,
                           __nv_bfloat16* __restrict__ lo)
{
    size_t stride = (size_t)gridDim.x * blockDim.x * 4;
    for (size_t i = ((size_t)blockIdx.x * blockDim.x + threadIdx.x) * 4;
         i < n; i += stride) {
        float4 v = *(const float4*)(s + i);
        __nv_bfloat16 hx = __float2bfloat16(v.x);
        __nv_bfloat16 hy = __float2bfloat16(v.y);
        __nv_bfloat16 hz = __float2bfloat16(v.z);
        __nv_bfloat16 hw = __float2bfloat16(v.w);
        __nv_bfloat16 lx = __float2bfloat16(v.x - __bfloat162float(hx));
        __nv_bfloat16 ly = __float2bfloat16(v.y - __bfloat162float(hy));
        __nv_bfloat16 lz = __float2bfloat16(v.z - __bfloat162float(hz));
        __nv_bfloat16 lw = __float2bfloat16(v.w - __bfloat162float(hw));
        *(__nv_bfloat162*)(hi + i)     = __nv_bfloat162(hx, hy);
        *(__nv_bfloat162*)(hi + i + 2) = __nv_bfloat162(hz, hw);
        *(__nv_bfloat162*)(lo + i)     = __nv_bfloat162(lx, ly);
        *(__nv_bfloat162*)(lo + i + 2) = __nv_bfloat162(lz, lw);
    }
}

__global__ void zero_cnt() { g_ncand = 0; }

// ---------------------------------------------------------------------------
// 2-split bf16 mma GEMM (NT): C = A@B^T via A1B1+A1B2+A2B1, fp32 regs.
// MODE 0: fp32 out.  MODE 1: fp32 out * QSCALE.
// MODE 2: int8 sign out + ambiguity candidates (|v| < TAU -> list).
// ---------------------------------------------------------------------------
#define RS   40
#define TILE_B (128 * RS * 2)          // 10240
#define BUF_B  (4 * TILE_B)            // 40960
#define MMA_SMEM  (2 * BUF_B)          // 81920
#define MMA4_SMEM (4 * BUF_B)          // 163840

template<int MODE>
__global__ void __launch_bounds__(256, 1)
mmah_gemm(const __nv_bfloat16* __restrict__ A1, const __nv_bfloat16* __restrict__ A2,
          const __nv_bfloat16* __restrict__ B1, const __nv_bfloat16* __restrict__ B2,
          void* __restrict__ Cv, uint32_t tag)
{
    extern __shared__ char sm[];
    const uint32_t smb = smem_u32(sm);
    const int tid = threadIdx.x, lane = tid & 31, w = tid >> 5;
    const int m0 = blockIdx.y * 128, n0 = blockIdx.x * 128;
    const int wm = (w & 3) * 32, wn = (w >> 2) * 64;

    const __nv_bfloat16* src[4] = {A1, A2, B1, B2};
    const int rbs[4] = {m0, m0, n0, n0};
    constexpr int NT = DM / 32;   // 64 stages

    auto issue = [&](int t) {
        const uint32_t bb = smb + (uint32_t)(t & 1) * BUF_B;
        const int k0 = t * 32;
#pragma unroll
        for (int i = 0; i < 2; i++) {
            const int c = tid + 256 * i;
            const int row = c >> 2, col8 = (c & 3) * 8;
#pragma unroll
            for (int X = 0; X < 4; X++) {
                uint32_t dst = bb + (uint32_t)X * TILE_B + row * (RS * 2) + col8 * 2;
                const __nv_bfloat16* s = src[X] + (size_t)(rbs[X] + row) * DM + k0 + col8;
                CPA(dst, s);
            }
        }
    };

    float acc[2][8][4];
#pragma unroll
    for (int mt = 0; mt < 2; mt++)
#pragma unroll
        for (int nt = 0; nt < 8; nt++)
#pragma unroll
            for (int e = 0; e < 4; e++) acc[mt][nt][e] = 0.f;

    issue(0); CPC();

    const int arow = wm + (lane & 15);
    const uint32_t acolo = ((lane >> 4) << 3) * 2;
    const int brow = wn + (lane & 7) + ((lane >> 4) << 3);
    const uint32_t bcolo = (((lane >> 3) & 1) << 3) * 2;

    for (int t = 0; t < NT; t++) {
        CPW0();
        __syncthreads();
        if (t + 1 < NT) { issue(t + 1); CPC(); }

        const uint32_t bb = smb + (uint32_t)(t & 1) * BUF_B;
#pragma unroll
        for (int ks = 0; ks < 32; ks += 16) {
            const uint32_t ko = (uint32_t)ks * 2;
            uint32_t a1f[2][4], a2f[2][4], b1f[8][2], b2f[8][2];
            ldsm4(a1f[0], bb + 0*TILE_B + (arow     ) * (RS*2) + ko + acolo);
            ldsm4(a1f[1], bb + 0*TILE_B + (arow + 16) * (RS*2) + ko + acolo);
            ldsm4(a2f[0], bb + 1*TILE_B + (arow     ) * (RS*2) + ko + acolo);
            ldsm4(a2f[1], bb + 1*TILE_B + (arow + 16) * (RS*2) + ko + acolo);
#pragma unroll
            for (int np = 0; np < 4; np++) {
                uint32_t r[4];
                ldsm4(r, bb + 2*TILE_B + (brow + np*16) * (RS*2) + ko + bcolo);
                b1f[np*2][0] = r[0]; b1f[np*2][1] = r[1];
                b1f[np*2+1][0] = r[2]; b1f[np*2+1][1] = r[3];
                ldsm4(r, bb + 3*TILE_B + (brow + np*16) * (RS*2) + ko + bcolo);
                b2f[np*2][0] = r[0]; b2f[np*2][1] = r[1];
                b2f[np*2+1][0] = r[2]; b2f[np*2+1][1] = r[3];
            }
#pragma unroll
            for (int mt = 0; mt < 2; mt++)
#pragma unroll
                for (int nt = 0; nt < 8; nt++) {
                    mma_bf16(acc[mt][nt], a1f[mt], b1f[nt]);
                    mma_bf16(acc[mt][nt], a1f[mt], b2f[nt]);
                    mma_bf16(acc[mt][nt], a2f[mt], b1f[nt]);
                }
        }
        __syncthreads();
    }

    if (MODE == 2) {
        int8_t* Cs = (int8_t*)Cv;
#pragma unroll
        for (int mt = 0; mt < 2; mt++)
#pragma unroll
            for (int nt = 0; nt < 8; nt++) {
                const int m = m0 + wm + mt * 16 + (lane >> 2);
                const int n = n0 + wn + nt * 8 + 2 * (lane & 3);
                const float* a = acc[mt][nt];
                char2 c01 = {(char)((a[0] >= 0.f) ? 1 : -1),
                             (char)((a[1] >= 0.f) ? 1 : -1)};
                char2 c23 = {(char)((a[2] >= 0.f) ? 1 : -1),
                             (char)((a[3] >= 0.f) ? 1 : -1)};
                *(char2*)&Cs[(size_t)m * DM + n]       = c01;
                *(char2*)&Cs[(size_t)(m + 8) * DM + n] = c23;
                const int mm[4] = {m, m, m + 8, m + 8};
                const int nn[4] = {n, n + 1, n, n + 1};
#pragma unroll
                for (int e = 0; e < 4; e++) {
                    if (fabsf(a[e]) < TAU) {
                        uint32_t idx = atomicAdd(&g_ncand, 1u);
                        if (idx < CAND_CAP)
                            g_cand[idx] = (tag << 25) |
                                          ((uint32_t)mm[e] << 11) | (uint32_t)nn[e];
                    }
                }
            }
    } else {
        float* C = (float*)Cv;
        const float s = (MODE == 1) ? QSCALE : 1.0f;
#pragma unroll
        for (int mt = 0; mt < 2; mt++)
#pragma unroll
            for (int nt = 0; nt < 8; nt++) {
                const int m = m0 + wm + mt * 16 + (lane >> 2);
                const int n = n0 + wn + nt * 8 + 2 * (lane & 3);
                float2 o0 = {acc[mt][nt][0] * s, acc[mt][nt][1] * s};
                float2 o1 = {acc[mt][nt][2] * s, acc[mt][nt][3] * s};
                *(float2*)&C[(size_t)m * DM + n]       = o0;
                *(float2*)&C[(size_t)(m + 8) * DM + n] = o1;
            }
    }
}

// ---------------------------------------------------------------------------
// Same GEMM, 4-stage cp.async ring — Wo (bit-identical accumulation order).
// ---------------------------------------------------------------------------
__global__ void __launch_bounds__(256, 1)
mmah_gemm4(const __nv_bfloat16* __restrict__ A1, const __nv_bfloat16* __restrict__ A2,
           const __nv_bfloat16* __restrict__ B1, const __nv_bfloat16* __restrict__ B2,
           float* __restrict__ C)
{
    extern __shared__ char sm[];
    const uint32_t smb = smem_u32(sm);
    const int tid = threadIdx.x, lane = tid & 31, w = tid >> 5;
    const int m0 = blockIdx.y * 128, n0 = blockIdx.x * 128;
    const int wm = (w & 3) * 32, wn = (w >> 2) * 64;

    const __nv_bfloat16* src[4] = {A1, A2, B1, B2};
    const int rbs[4] = {m0, m0, n0, n0};
    constexpr int NT = DM / 32;

    auto issue = [&](int t) {
        const uint32_t bb = smb + (uint32_t)(t & 3) * BUF_B;
        const int k0 = t * 32;
#pragma unroll
        for (int i = 0; i < 2; i++) {
            const int c = tid + 256 * i;
            const int row = c >> 2, col8 = (c & 3) * 8;
#pragma unroll
            for (int X = 0; X < 4; X++) {
                uint32_t dst = bb + (uint32_t)X * TILE_B + row * (RS * 2) + col8 * 2;
                const __nv_bfloat16* s = src[X] + (size_t)(rbs[X] + row) * DM + k0 + col8;
                CPA(dst, s);
            }
        }
    };

    float acc[2][8][4];
#pragma unroll
    for (int mt = 0; mt < 2; mt++)
#pragma unroll
        for (int nt = 0; nt < 8; nt++)
#pragma unroll
            for (int e = 0; e < 4; e++) acc[mt][nt][e] = 0.f;

    issue(0); CPC(); issue(1); CPC(); issue(2); CPC();

    const int arow = wm + (lane & 15);
    const uint32_t acolo = ((lane >> 4) << 3) * 2;
    const int brow = wn + (lane & 7) + ((lane >> 4) << 3);
    const uint32_t bcolo = (((lane >> 3) & 1) << 3) * 2;

    for (int t = 0; t < NT; t++) {
        CPW2();
        __syncthreads();
        if (t + 3 < NT) { issue(t + 3); CPC(); }

        const uint32_t bb = smb + (uint32_t)(t & 3) * BUF_B;
#pragma unroll
        for (int ks = 0; ks < 32; ks += 16) {
            const uint32_t ko = (uint32_t)ks * 2;
            uint32_t a1f[2][4], a2f[2][4], b1f[8][2], b2f[8][2];
            ldsm4(a1f[0], bb + 0*TILE_B + (arow     ) * (RS*2) + ko + acolo);
            ldsm4(a1f[1], bb + 0*TILE_B + (arow + 16) * (RS*2) + ko + acolo);
            ldsm4(a2f[0], bb + 1*TILE_B + (arow     ) * (RS*2) + ko + acolo);
            ldsm4(a2f[1], bb + 1*TILE_B + (arow + 16) * (RS*2) + ko + acolo);
#pragma unroll
            for (int np = 0; np < 4; np++) {
                uint32_t r[4];
                ldsm4(r, bb + 2*TILE_B + (brow + np*16) * (RS*2) + ko + bcolo);
                b1f[np*2][0] = r[0]; b1f[np*2][1] = r[1];
                b1f[np*2+1][0] = r[2]; b1f[np*2+1][1] = r[3];
                ldsm4(r, bb + 3*TILE_B + (brow + np*16) * (RS*2) + ko + bcolo);
                b2f[np*2][0] = r[0]; b2f[np*2][1] = r[1];
                b2f[np*2+1][0] = r[2]; b2f[np*2+1][1] = r[3];
            }
#pragma unroll
            for (int mt = 0; mt < 2; mt++)
#pragma unroll
                for (int nt = 0; nt < 8; nt++) {
                    mma_bf16(acc[mt][nt], a1f[mt], b1f[nt]);
                    mma_bf16(acc[mt][nt], a1f[mt], b2f[nt]);
                    mma_bf16(acc[mt][nt], a2f[mt], b1f[nt]);
                }
        }
    }

#pragma unroll
    for (int mt = 0; mt < 2; mt++)
#pragma unroll
        for (int nt = 0; nt < 8; nt++) {
            const int m = m0 + wm + mt * 16 + (lane >> 2);
            const int n = n0 + wn + nt * 8 + 2 * (lane & 3);
            float2 o0 = {acc[mt][nt][0], acc[mt][nt][1]};
            float2 o1 = {acc[mt][nt][2], acc[mt][nt][3]};
            *(float2*)&C[(size_t)m * DM + n]       = o0;
            *(float2*)&C[(size_t)(m + 8) * DM + n] = o1;
        }
}

// ---------------------------------------------------------------------------
// Fixup: recompute each ambiguous element with the EXACT arithmetic of the
// validated R5 fp32 gemm_nt path (per-lane f2_fma == scalar IEEE fmaf):
//   32 segments of 64 sequential fmaf in increasing k; acc += segment.
// Result: signs bit-identical to the previously passing kernel.
// ---------------------------------------------------------------------------
__global__ void __launch_bounds__(256)
fixup(const float* __restrict__ x, const float* __restrict__ Wk,
      const float* __restrict__ Wv)
{
    uint32_t ncand = g_ncand;
    if (ncand > CAND_CAP) ncand = CAND_CAP;
    const uint32_t total = gridDim.x * blockDim.x;
    for (uint32_t i = blockIdx.x * blockDim.x + threadIdx.x; i < ncand;
         i += total) {
        const uint32_t c = g_cand[i];
        const int col = c & 2047;
        const int m   = (c >> 11) & 16383;
        const int tag = c >> 25;
        const float* a = x + (size_t)m * DM;
        const float* b = (tag ? Wv : Wk) + (size_t)col * DM;
        float acc = 0.f;
        for (int s = 0; s < 32; s++) {
            float tmp = 0.f;
            const float* as = a + s * 64;
            const float* bs = b + s * 64;
#pragma unroll
            for (int k4 = 0; k4 < 64; k4 += 4) {
                float4 av = *(const float4*)(as + k4);
                float4 bv = *(const float4*)(bs + k4);
                tmp = fmaf(av.x, bv.x, tmp);
                tmp = fmaf(av.y, bv.y, tmp);
                tmp = fmaf(av.z, bv.z, tmp);
                tmp = fmaf(av.w, bv.w, tmp);
            }
            acc += tmp;
        }
        int8_t* dst = tag ? g_v : g_k;
        dst[(size_t)m * DM + col] = (acc >= 0.f) ? (int8_t)1 : (int8_t)-1;
    }
}

// ---------------------------------------------------------------------------
// Attention scan (validated; epilogue writes bf16 2-split of output).
// ---------------------------------------------------------------------------
struct AttSmem {
    float  qcT[128][132];
    float  scoresT[128][132];
    float  state[128][68];
    int8_t kc[128][144];
    int8_t kT[128][144];
    int8_t vc[128][80];
};

__device__ __forceinline__ void b4_to_f(unsigned w, float* f) {
    f[0] = (float)((int)(w << 24) >> 24);
    f[1] = (float)((int)(w << 16) >> 24);
    f[2] = (float)((int)(w <<  8) >> 24);
    f[3] = (float)((int) w        >> 24);
}

__global__ void __launch_bounds__(256)
att_kernel(const float* __restrict__ gq, const int8_t* __restrict__ gk,
           const int8_t* __restrict__ gv,
           __nv_bfloat16* __restrict__ ga1, __nv_bfloat16* __restrict__ ga2,
           float* __restrict__ gstate, int write_state)
{
    extern __shared__ char sraw[];
    AttSmem& S = *(AttSmem*)sraw;

    const int pair = blockIdx.x;
    const int half = pair & 1;
    const int bh   = pair >> 1;
    const int b    = bh >> 4, h = bh & 15;
    const int tid  = threadIdx.x;

    for (int i = tid; i < 128 * 68; i += 256)
        ((float*)S.state)[i] = 0.f;

    const int ty = tid >> 4, tx = tid & 15;
    const int i0 = ty * 8, j0 = tx * 8, e0 = tx * 4;

    const size_t base_row = (size_t)b * SEQ;
    const int colq = h * DH;
    const int colv = h * DH + half * 64;

    const int lc = tid >> 1;
    const int dh = (tid & 1) * 64;

    for (int n = 0; n < 32; n++) {
        {
            const size_t row = base_row + (size_t)n * 128 + lc;
            const float* qs = gq + row * DM + colq + dh;
#pragma unroll
            for (int d4 = 0; d4 < 64; d4 += 4) {
                float4 v = *(const float4*)(qs + d4);
                S.qcT[dh + d4 + 0][lc] = v.x;
                S.qcT[dh + d4 + 1][lc] = v.y;
                S.qcT[dh + d4 + 2][lc] = v.z;
                S.qcT[dh + d4 + 3][lc] = v.w;
            }
            const int8_t* ks = gk + row * DM + colq + dh;
#pragma unroll
            for (int d16 = 0; d16 < 64; d16 += 16) {
                int4 kw = *(const int4*)(ks + d16);
                *(int4*)&S.kc[lc][dh + d16] = kw;
                const int8_t* kb = (const int8_t*)&kw;
#pragma unroll
                for (int z = 0; z < 16; z++)
                    S.kT[dh + d16 + z][lc] = kb[z];
            }
            const int8_t* vs = gv + row * DM + colv + (dh >> 1);
            *(int4*)&S.vc[lc][(dh >> 1) + 0]  = *(const int4*)(vs);
            *(int4*)&S.vc[lc][(dh >> 1) + 16] = *(const int4*)(vs + 16);
        }
        __syncthreads();

        float sc[8][8], cr[8][4];
#pragma unroll
        for (int i = 0; i < 8; i++) {
#pragma unroll
            for (int j = 0; j < 8; j++) sc[i][j] = 0.f;
#pragma unroll
            for (int e = 0; e < 4; e++) cr[i][e] = 0.f;
        }
        for (int kk = 0; kk < 128; kk++) {
            float4 q0 = *(const float4*)&S.qcT[kk][i0];
            float4 q1 = *(const float4*)&S.qcT[kk][i0 + 4];
            float qv[8] = {q0.x, q0.y, q0.z, q0.w, q1.x, q1.y, q1.z, q1.w};
            uint2 kw = *(const uint2*)&S.kT[kk][j0];
            float kf[8];
            b4_to_f(kw.x, kf); b4_to_f(kw.y, kf + 4);
            float4 st = *(const float4*)&S.state[kk][e0];
            float sf[4] = {st.x, st.y, st.z, st.w};
#pragma unroll
            for (int i = 0; i < 8; i++) {
#pragma unroll
                for (int j = 0; j < 8; j++)
                    sc[i][j] = fmaf(qv[i], kf[j], sc[i][j]);
#pragma unroll
                for (int e = 0; e < 4; e++)
                    cr[i][e] = fmaf(qv[i], sf[e], cr[i][e]);
            }
        }
#pragma unroll
        for (int jj = 0; jj < 8; jj++)
#pragma unroll
            for (int ii = 0; ii < 8; ii++) {
                int gi = i0 + ii, gj = j0 + jj;
                S.scoresT[gj][gi] = (gj <= gi) ? sc[ii][jj] : 0.f;
            }
        __syncthreads();

        float in8[8][4], up[8][4];
#pragma unroll
        for (int i = 0; i < 8; i++)
#pragma unroll
            for (int e = 0; e < 4; e++) { in8[i][e] = 0.f; up[i][e] = 0.f; }

        for (int kk = 0; kk < 128; kk++) {
            float4 s0 = *(const float4*)&S.scoresT[kk][i0];
            float4 s1 = *(const float4*)&S.scoresT[kk][i0 + 4];
            float sv[8] = {s0.x, s0.y, s0.z, s0.w, s1.x, s1.y, s1.z, s1.w};
            uint2 kw = *(const uint2*)&S.kc[kk][i0];
            float kf[8];
            b4_to_f(kw.x, kf); b4_to_f(kw.y, kf + 4);
            unsigned vw = *(const unsigned*)&S.vc[kk][e0];
            float vf[4];
            b4_to_f(vw, vf);
#pragma unroll
            for (int i = 0; i < 8; i++)
#pragma unroll
                for (int e = 0; e < 4; e++) {
                    in8[i][e] = fmaf(sv[i], vf[e], in8[i][e]);
                    up[i][e]  = fmaf(kf[i], vf[e], up[i][e]);
                }
        }
#pragma unroll
        for (int ii = 0; ii < 8; ii++) {
            size_t row = (base_row + (size_t)n * 128 + i0 + ii) * DM + colv + e0;
            float o[4] = {cr[ii][0] + in8[ii][0], cr[ii][1] + in8[ii][1],
                          cr[ii][2] + in8[ii][2], cr[ii][3] + in8[ii][3]};
            __nv_bfloat16 hb[4], lb[4];
#pragma unroll
            for (int e = 0; e < 4; e++) {
                hb[e] = __float2bfloat16(o[e]);
                lb[e] = __float2bfloat16(o[e] - __bfloat162float(hb[e]));
            }
            *(__nv_bfloat162*)(ga1 + row)     = __nv_bfloat162(hb[0], hb[1]);
            *(__nv_bfloat162*)(ga1 + row + 2) = __nv_bfloat162(hb[2], hb[3]);
            *(__nv_bfloat162*)(ga2 + row)     = __nv_bfloat162(lb[0], lb[1]);
            *(__nv_bfloat162*)(ga2 + row + 2) = __nv_bfloat162(lb[2], lb[3]);
#pragma unroll
            for (int e = 0; e < 4; e++)
                S.state[i0 + ii][e0 + e] += up[ii][e];
        }
        __syncthreads();
    }

    if (write_state) {
        for (int idx = tid; idx < 128 * 64; idx += 256) {
            int d = idx >> 6, e = idx & 63;
            gstate[(((size_t)(b * NH + h) * DH) + d) * DH + half * 64 + e]
                = S.state[d][e];
        }
    }
}

// ---------------------------------------------------------------------------
extern "C" void kernel_launch(void* const* d_in, const int* in_sizes, int n_in,
                              void* d_out, int out_size)
{
    const float* x  = (const float*)d_in[0];
    const float* Wq = (const float*)d_in[1];
    const float* Wk = (const float*)d_in[2];
    const float* Wv = (const float*)d_in[3];
    const float* Wo = (const float*)d_in[4];
    float* out = (float*)d_out;

    void *pq, *pk, *pv;
    void *px1, *px2, *pa1, *pa2;
    void *pwq1, *pwq2, *pwk1, *pwk2, *pwv1, *pwv2, *pwo1, *pwo2;
    cudaGetSymbolAddress(&pq,  g_q);
    cudaGetSymbolAddress(&pk,  g_k);
    cudaGetSymbolAddress(&pv,  g_v);
    cudaGetSymbolAddress(&px1, g_x1);
    cudaGetSymbolAddress(&px2, g_x2);
    cudaGetSymbolAddress(&pa1, g_a1);
    cudaGetSymbolAddress(&pa2, g_a2);
    cudaGetSymbolAddress(&pwq1, g_wq1);
    cudaGetSymbolAddress(&pwq2, g_wq2);
    cudaGetSymbolAddress(&pwk1, g_wk1);
    cudaGetSymbolAddress(&pwk2, g_wk2);
    cudaGetSymbolAddress(&pwv1, g_wv1);
    cudaGetSymbolAddress(&pwv2, g_wv2);
    cudaGetSymbolAddress(&pwo1, g_wo1);
    cudaGetSymbolAddress(&pwo2, g_wo2);

    cudaFuncSetAttribute(mmah_gemm<1>, cudaFuncAttributeMaxDynamicSharedMemorySize, MMA_SMEM);
    cudaFuncSetAttribute(mmah_gemm<2>, cudaFuncAttributeMaxDynamicSharedMemorySize, MMA_SMEM);
    cudaFuncSetAttribute(mmah_gemm4,  cudaFuncAttributeMaxDynamicSharedMemorySize, MMA4_SMEM);
    cudaFuncSetAttribute(att_kernel, cudaFuncAttributeMaxDynamicSharedMemorySize,
                         (int)sizeof(AttSmem));

    zero_cnt<<<1, 1>>>();
    split_bf16<<<8192, 256>>>(x, (size_t)MROWS * DM,
                              (__nv_bfloat16*)px1, (__nv_bfloat16*)px2);
    split_bf16<<<1024, 256>>>(Wq, (size_t)DM * DM,
                              (__nv_bfloat16*)pwq1, (__nv_bfloat16*)pwq2);
    split_bf16<<<1024, 256>>>(Wk, (size_t)DM * DM,
                              (__nv_bfloat16*)pwk1, (__nv_bfloat16*)pwk2);
    split_bf16<<<1024, 256>>>(Wv, (size_t)DM * DM,
                              (__nv_bfloat16*)pwv1, (__nv_bfloat16*)pwv2);
    split_bf16<<<1024, 256>>>(Wo, (size_t)DM * DM,
                              (__nv_bfloat16*)pwo1, (__nv_bfloat16*)pwo2);

    dim3 grid(DM / 128, MROWS / 128), blk(256);
    // Q projection (scaled fp32 out)
    mmah_gemm<1><<<grid, blk, MMA_SMEM>>>(
        (const __nv_bfloat16*)px1, (const __nv_bfloat16*)px2,
        (const __nv_bfloat16*)pwq1, (const __nv_bfloat16*)pwq2, pq, 0u);
    // K/V sign projections on tensor cores + ambiguity candidates
    mmah_gemm<2><<<grid, blk, MMA_SMEM>>>(
        (const __nv_bfloat16*)px1, (const __nv_bfloat16*)px2,
        (const __nv_bfloat16*)pwk1, (const __nv_bfloat16*)pwk2, pk, 0u);
    mmah_gemm<2><<<grid, blk, MMA_SMEM>>>(
        (const __nv_bfloat16*)px1, (const __nv_bfloat16*)px2,
        (const __nv_bfloat16*)pwv1, (const __nv_bfloat16*)pwv2, pv, 1u);
    // exact-replay fixup (reproduces the validated fp32 gemm_nt signs bitwise)
    fixup<<<256, 256>>>(x, Wk, Wv);

    int write_state = ((size_t)out_size >= OUT_ELEMS + STATE_ELEMS) ? 1 : 0;
    att_kernel<<<128, 256, sizeof(AttSmem)>>>(
        (const float*)pq, (const int8_t*)pk, (const int8_t*)pv,
        (__nv_bfloat16*)pa1, (__nv_bfloat16*)pa2, out + OUT_ELEMS, write_state);

    mmah_gemm4<<<grid, blk, MMA4_SMEM>>>(
        (const __nv_bfloat16*)pa1, (const __nv_bfloat16*)pa2,
        (const __nv_bfloat16*)pwo1, (const __nv_bfloat16*)pwo2, out);
}